// round 1
// baseline (speedup 1.0000x reference)
#include <cuda_runtime.h>
#include <math.h>
#include <stdint.h>

#define NN 100000
#define EE 3200000
#define EA (EE + NN)
#define FIN 78
#define FG 256
#define FH 128

// ---------------- scratch (device globals; no allocation) ----------------
__device__ float d_xh[(size_t)NN * 512];
__device__ float d_h [(size_t)NN * 256];
__device__ float d_x [(size_t)NN * 256];
__device__ float d_g [(size_t)NN * 256];
__device__ float d_hx[(size_t)NN * 334];
__device__ float d_xt[(size_t)NN * 128];
__device__ float d_ef[(size_t)NN * 128];
__device__ float d_hy[(size_t)NN * 128];
__device__ float d_asrc[NN * 2];
__device__ float d_adst[NN * 2];
__device__ float2 d_alpha[EA];
__device__ int csrA_off[NN + 1]; __device__ int csrA_val[EA];
__device__ int csrB_off[NN + 1]; __device__ int csrB_val[EE];
__device__ int csrC_off[NN + 1]; __device__ int csrC_val[EE];
__device__ int cntA[NN], cntB[NN], cntC[NN];
__device__ int curA[NN], curB[NN], curC[NN];
__device__ float d_binv[NN], d_dinv[NN];

// ---------------- CSR construction ----------------
__global__ void zero_counts_kernel() {
    int i = blockIdx.x * blockDim.x + threadIdx.x;
    if (i < NN) { cntA[i] = 0; cntB[i] = 0; cntC[i] = 0; }
}

__global__ void count_kernel(const int* __restrict__ ei) {
    int i = blockIdx.x * blockDim.x + threadIdx.x;
    if (i >= EA) return;
    if (i < EE) {
        int s = ei[i];
        int d = ei[EE + i];
        atomicAdd(&cntA[d], 1);
        atomicAdd(&cntB[d], 1);
        atomicAdd(&cntC[s], 1);
    } else {
        atomicAdd(&cntA[i - EE], 1);  // self loop
    }
}

// single-block exclusive scan; out has n+1 entries
__global__ void scan_kernel(const int* __restrict__ in, int* __restrict__ out, int n) {
    __shared__ int wsum[32];
    __shared__ int carry;
    int tid = threadIdx.x, lane = tid & 31, wid = tid >> 5;
    if (tid == 0) carry = 0;
    __syncthreads();
    for (int base = 0; base < n; base += 1024) {
        int i = base + tid;
        int v = (i < n) ? in[i] : 0;
        int x = v;
        #pragma unroll
        for (int d = 1; d < 32; d <<= 1) {
            int y = __shfl_up_sync(0xFFFFFFFFu, x, d);
            if (lane >= d) x += y;
        }
        if (lane == 31) wsum[wid] = x;
        __syncthreads();
        if (wid == 0) {
            int w = wsum[lane];
            #pragma unroll
            for (int d = 1; d < 32; d <<= 1) {
                int y = __shfl_up_sync(0xFFFFFFFFu, w, d);
                if (lane >= d) w += y;
            }
            wsum[lane] = w;
        }
        __syncthreads();
        int excl = carry + (wid ? wsum[wid - 1] : 0) + x - v;
        if (i < n) out[i] = excl;
        if (i == n - 1) out[n] = excl + v;
        __syncthreads();
        if (tid == 0) carry += wsum[31];
        __syncthreads();
    }
}

__global__ void prep_kernel() {
    int i = blockIdx.x * blockDim.x + threadIdx.x;
    if (i >= NN) return;
    curA[i] = csrA_off[i];
    curB[i] = csrB_off[i];
    curC[i] = csrC_off[i];
    d_binv[i] = cntB[i] > 0 ? 1.0f / (float)cntB[i] : 0.0f;
    d_dinv[i] = cntC[i] > 0 ? 1.0f / (float)cntC[i] : 0.0f;
}

__global__ void fill_kernel(const int* __restrict__ ei) {
    int i = blockIdx.x * blockDim.x + threadIdx.x;
    if (i >= EA) return;
    if (i < EE) {
        int s = ei[i];
        int d = ei[EE + i];
        csrA_val[atomicAdd(&curA[d], 1)] = s;
        csrB_val[atomicAdd(&curB[d], 1)] = s;
        csrC_val[atomicAdd(&curC[s], 1)] = d;
    } else {
        int n = i - EE;
        csrA_val[atomicAdd(&curA[n], 1)] = n;
    }
}

// ---------------- SGEMM: C[M,Nc] = A[M,K] @ B (opt transB) ----------------
// 128x128 tile, BK=8, 256 threads, 8x8 per thread.
template <bool TRANSB, bool ACC>
__global__ void sgemm_kernel(const float* __restrict__ A, const float* __restrict__ B,
                             float* __restrict__ C, int M, int Nc, int K,
                             const float* __restrict__ bias, int relu) {
    __shared__ float As[8][128];
    __shared__ float Bs[8][128];
    int tid = threadIdx.x;
    int row0 = blockIdx.y * 128;
    int col0 = blockIdx.x * 128;
    int ty = tid >> 4;       // 0..15
    int tx = tid & 15;       // 0..15
    float acc[8][8];
    #pragma unroll
    for (int m = 0; m < 8; m++)
        #pragma unroll
        for (int n = 0; n < 8; n++) acc[m][n] = 0.0f;

    for (int k0 = 0; k0 < K; k0 += 8) {
        #pragma unroll
        for (int i = 0; i < 4; i++) {
            int l = tid + i * 256;
            int r = l >> 3, kk = l & 7;
            int gr = row0 + r, gk = k0 + kk;
            float v = 0.0f;
            if (gr < M && gk < K) v = A[(size_t)gr * K + gk];
            As[kk][r] = v;
        }
        #pragma unroll
        for (int i = 0; i < 4; i++) {
            int l = tid + i * 256;
            float v = 0.0f;
            if (!TRANSB) {
                int kk = l >> 7, n = l & 127;
                int gk = k0 + kk, gn = col0 + n;
                if (gk < K && gn < Nc) v = B[(size_t)gk * Nc + gn];
                Bs[kk][n] = v;
            } else {
                int n = l >> 3, kk = l & 7;
                int gk = k0 + kk, gn = col0 + n;
                if (gk < K && gn < Nc) v = B[(size_t)gn * K + gk];
                Bs[kk][n] = v;
            }
        }
        __syncthreads();
        #pragma unroll
        for (int kk = 0; kk < 8; kk++) {
            float ra[8], rb[8];
            float4 a0 = *(const float4*)&As[kk][ty * 8];
            float4 a1 = *(const float4*)&As[kk][ty * 8 + 4];
            float4 b0 = *(const float4*)&Bs[kk][tx * 8];
            float4 b1 = *(const float4*)&Bs[kk][tx * 8 + 4];
            ra[0]=a0.x; ra[1]=a0.y; ra[2]=a0.z; ra[3]=a0.w;
            ra[4]=a1.x; ra[5]=a1.y; ra[6]=a1.z; ra[7]=a1.w;
            rb[0]=b0.x; rb[1]=b0.y; rb[2]=b0.z; rb[3]=b0.w;
            rb[4]=b1.x; rb[5]=b1.y; rb[6]=b1.z; rb[7]=b1.w;
            #pragma unroll
            for (int m = 0; m < 8; m++)
                #pragma unroll
                for (int n = 0; n < 8; n++)
                    acc[m][n] += ra[m] * rb[n];
        }
        __syncthreads();
    }
    #pragma unroll
    for (int m = 0; m < 8; m++) {
        int gr = row0 + ty * 8 + m;
        if (gr >= M) continue;
        #pragma unroll
        for (int n = 0; n < 8; n++) {
            int gn = col0 + tx * 8 + n;
            if (gn >= Nc) continue;
            float v = acc[m][n];
            if (bias) v += bias[gn];
            if (ACC) v += C[(size_t)gr * Nc + gn];
            if (relu) v = fmaxf(v, 0.0f);
            C[(size_t)gr * Nc + gn] = v;
        }
    }
}

// ---------------- GAT pieces ----------------
// a_src[n,h] = dot(xh[n,h,:], a_s[h,:]); a_dst similarly. warp per (n,h).
__global__ void attn_kernel(const float* __restrict__ xh,
                            const float* __restrict__ a_s,
                            const float* __restrict__ a_d) {
    int warp = threadIdx.x >> 5, lane = threadIdx.x & 31;
    int idx = blockIdx.x * 4 + warp;
    if (idx >= NN * 2) return;
    int n = idx >> 1, h = idx & 1;
    const float* row = xh + (size_t)n * 512 + h * 256;
    const float* as = a_s + h * 256;
    const float* ad = a_d + h * 256;
    float s1 = 0.0f, s2 = 0.0f;
    #pragma unroll
    for (int c = lane; c < 256; c += 32) {
        float v = row[c];
        s1 += v * as[c];
        s2 += v * ad[c];
    }
    #pragma unroll
    for (int d = 16; d; d >>= 1) {
        s1 += __shfl_down_sync(0xFFFFFFFFu, s1, d);
        s2 += __shfl_down_sync(0xFFFFFFFFu, s2, d);
    }
    if (lane == 0) { d_asrc[idx] = s1; d_adst[idx] = s2; }
}

__device__ __forceinline__ float lrelu02(float v) { return v >= 0.0f ? v : 0.2f * v; }

// warp per destination node: segment softmax over csrA, writes alpha (float2 per pos)
__global__ void softmax_kernel() {
    int n = blockIdx.x * (blockDim.x >> 5) + (threadIdx.x >> 5);
    int lane = threadIdx.x & 31;
    if (n >= NN) return;
    int s0 = csrA_off[n], s1 = csrA_off[n + 1];
    float ad0 = d_adst[n * 2], ad1 = d_adst[n * 2 + 1];
    float m0 = -1e30f, m1 = -1e30f;
    for (int p = s0 + lane; p < s1; p += 32) {
        int src = csrA_val[p];
        float e0 = lrelu02(d_asrc[src * 2] + ad0);
        float e1 = lrelu02(d_asrc[src * 2 + 1] + ad1);
        m0 = fmaxf(m0, e0); m1 = fmaxf(m1, e1);
    }
    #pragma unroll
    for (int d = 16; d; d >>= 1) {
        m0 = fmaxf(m0, __shfl_xor_sync(0xFFFFFFFFu, m0, d));
        m1 = fmaxf(m1, __shfl_xor_sync(0xFFFFFFFFu, m1, d));
    }
    float sum0 = 0.0f, sum1 = 0.0f;
    for (int p = s0 + lane; p < s1; p += 32) {
        int src = csrA_val[p];
        float e0 = lrelu02(d_asrc[src * 2] + ad0);
        float e1 = lrelu02(d_asrc[src * 2 + 1] + ad1);
        float x0 = __expf(e0 - m0), x1 = __expf(e1 - m1);
        d_alpha[p] = make_float2(x0, x1);
        sum0 += x0; sum1 += x1;
    }
    #pragma unroll
    for (int d = 16; d; d >>= 1) {
        sum0 += __shfl_xor_sync(0xFFFFFFFFu, sum0, d);
        sum1 += __shfl_xor_sync(0xFFFFFFFFu, sum1, d);
    }
    float r0 = 1.0f / sum0, r1 = 1.0f / sum1;
    for (int p = s0 + lane; p < s1; p += 32) {
        float2 a = d_alpha[p];
        a.x *= r0; a.y *= r1;
        d_alpha[p] = a;
    }
}

// block(256) per destination node: out[n,:] = mean_h sum_e alpha*xh[src] + b
__global__ void gat_aggregate_kernel(const float* __restrict__ xh,
                                     const float* __restrict__ bias,
                                     float* __restrict__ out, int relu) {
    int n = blockIdx.x;
    int t = threadIdx.x;
    int s0 = csrA_off[n], s1 = csrA_off[n + 1];
    float acc0 = 0.0f, acc1 = 0.0f;
    __shared__ int ssrc[256];
    __shared__ float2 salp[256];
    for (int base = s0; base < s1; base += 256) {
        int cnt = min(256, s1 - base);
        __syncthreads();
        if (t < cnt) { ssrc[t] = csrA_val[base + t]; salp[t] = d_alpha[base + t]; }
        __syncthreads();
        #pragma unroll 4
        for (int j = 0; j < cnt; j++) {
            int s = ssrc[j];
            float2 a = salp[j];
            const float* row = xh + (size_t)s * 512;
            acc0 += a.x * row[t];
            acc1 += a.y * row[256 + t];
        }
    }
    float v = 0.5f * (acc0 + acc1) + bias[t];
    if (relu) v = fmaxf(v, 0.0f);
    out[(size_t)n * 256 + t] = v;
}

// h = z*x + (1-z)*h,  z = sigmoid(G + mol_bias)
__global__ void gate_kernel(const float* __restrict__ x, float* __restrict__ h,
                            const float* __restrict__ G, const float* __restrict__ mol_bias) {
    size_t i = (size_t)blockIdx.x * blockDim.x + threadIdx.x;
    if (i >= (size_t)NN * 256) return;
    int col = (int)(i & 255);
    float v = G[i] + mol_bias[col];
    float z = 1.0f / (1.0f + __expf(-v));
    h[i] = z * x[i] + (1.0f - z) * h[i];
}

// ---------------- hypergraph ----------------
__global__ void concat_kernel(const float* __restrict__ h, const float* __restrict__ mol_x,
                              float* __restrict__ hx) {
    size_t i = (size_t)blockIdx.x * blockDim.x + threadIdx.x;
    if (i >= (size_t)NN * 334) return;
    int n = (int)(i / 334);
    int c = (int)(i % 334);
    hx[i] = (c < 256) ? h[(size_t)n * 256 + c] : mol_x[(size_t)n * FIN + (c - 256)];
}

// which=0: group by csrB (edge), scale Binv ; which=1: group by csrC (node), scale Dinv
__global__ void hyper_gather_kernel(const float* __restrict__ in, float* __restrict__ out,
                                    const float* __restrict__ bias, int which, int relu) {
    const int* off = which ? csrC_off : csrB_off;
    const int* val = which ? csrC_val : csrB_val;
    const float* inv = which ? d_dinv : d_binv;
    int n = blockIdx.x;
    int t = threadIdx.x;
    int s0 = off[n], s1 = off[n + 1];
    float acc = 0.0f;
    __shared__ int sv[128];
    for (int base = s0; base < s1; base += 128) {
        int cnt = min(128, s1 - base);
        __syncthreads();
        if (t < cnt) sv[t] = val[base + t];
        __syncthreads();
        #pragma unroll 4
        for (int j = 0; j < cnt; j++)
            acc += in[(size_t)sv[j] * FH + t];
    }
    float v = acc * inv[n];
    if (bias) v += bias[t];
    if (relu) v = fmaxf(v, 0.0f);
    out[(size_t)n * FH + t] = v;
}

__global__ void output_kernel(const float* __restrict__ h, const float* __restrict__ hy,
                              float* __restrict__ out) {
    size_t i = (size_t)blockIdx.x * blockDim.x + threadIdx.x;
    if (i >= (size_t)NN * 384) return;
    int n = (int)(i / 384);
    int c = (int)(i % 384);
    out[i] = (c < 256) ? h[(size_t)n * 256 + c] : hy[(size_t)n * FH + (c - 256)];
}

// ---------------- host side ----------------
static void run_gemm(const float* A, const float* B, float* C, int M, int Nc, int K,
                     const float* bias, int relu, bool transB, bool acc) {
    dim3 grid((Nc + 127) / 128, (M + 127) / 128);
    if (transB) {
        if (acc) sgemm_kernel<true, true><<<grid, 256>>>(A, B, C, M, Nc, K, bias, relu);
        else     sgemm_kernel<true, false><<<grid, 256>>>(A, B, C, M, Nc, K, bias, relu);
    } else {
        if (acc) sgemm_kernel<false, true><<<grid, 256>>>(A, B, C, M, Nc, K, bias, relu);
        else     sgemm_kernel<false, false><<<grid, 256>>>(A, B, C, M, Nc, K, bias, relu);
    }
}

extern "C" void kernel_launch(void* const* d_in, const int* in_sizes, int n_in,
                              void* d_out, int out_size) {
    const float* mol_x = (const float*)d_in[0];
    const int*   ei    = (const int*)d_in[1];
    // d_in[2] = hyper_edge (unused by the reference forward)
    const float* W1 = (const float*)d_in[3];
    const float* as1 = (const float*)d_in[4];
    const float* ad1 = (const float*)d_in[5];
    const float* b1 = (const float*)d_in[6];
    const float* W2 = (const float*)d_in[7];
    const float* as2 = (const float*)d_in[8];
    const float* ad2 = (const float*)d_in[9];
    const float* b2 = (const float*)d_in[10];
    const float* W3 = (const float*)d_in[11];
    const float* as3 = (const float*)d_in[12];
    const float* ad3 = (const float*)d_in[13];
    const float* b3 = (const float*)d_in[14];
    const float* fc1_w = (const float*)d_in[15];
    const float* fc1_b = (const float*)d_in[16];
    const float* fc2_w = (const float*)d_in[17];
    const float* fc2_b = (const float*)d_in[18];
    const float* mol_bias = (const float*)d_in[19];
    const float* theta1 = (const float*)d_in[20];
    const float* hb1 = (const float*)d_in[21];
    const float* theta2 = (const float*)d_in[22];
    const float* hb2 = (const float*)d_in[23];

    float *p_xh, *p_h, *p_x, *p_g, *p_hx, *p_xt, *p_ef, *p_hy;
    cudaGetSymbolAddress((void**)&p_xh, d_xh);
    cudaGetSymbolAddress((void**)&p_h, d_h);
    cudaGetSymbolAddress((void**)&p_x, d_x);
    cudaGetSymbolAddress((void**)&p_g, d_g);
    cudaGetSymbolAddress((void**)&p_hx, d_hx);
    cudaGetSymbolAddress((void**)&p_xt, d_xt);
    cudaGetSymbolAddress((void**)&p_ef, d_ef);
    cudaGetSymbolAddress((void**)&p_hy, d_hy);

    // ---- CSR build (per call; deterministic) ----
    zero_counts_kernel<<<(NN + 255) / 256, 256>>>();
    count_kernel<<<(EA + 255) / 256, 256>>>(ei);
    {
        int *pcA, *pcB, *pcC, *poA, *poB, *poC;
        cudaGetSymbolAddress((void**)&pcA, cntA);
        cudaGetSymbolAddress((void**)&pcB, cntB);
        cudaGetSymbolAddress((void**)&pcC, cntC);
        cudaGetSymbolAddress((void**)&poA, csrA_off);
        cudaGetSymbolAddress((void**)&poB, csrB_off);
        cudaGetSymbolAddress((void**)&poC, csrC_off);
        scan_kernel<<<1, 1024>>>(pcA, poA, NN);
        scan_kernel<<<1, 1024>>>(pcB, poB, NN);
        scan_kernel<<<1, 1024>>>(pcC, poC, NN);
    }
    prep_kernel<<<(NN + 255) / 256, 256>>>();
    fill_kernel<<<(EA + 255) / 256, 256>>>(ei);

    // ---- GAT layer 1: h = relu(gat(mol_x)) ----
    run_gemm(mol_x, W1, p_xh, NN, 512, FIN, nullptr, 0, false, false);
    attn_kernel<<<(NN * 2 + 3) / 4, 128>>>(p_xh, as1, ad1);
    softmax_kernel<<<(NN + 7) / 8, 256>>>();
    gat_aggregate_kernel<<<NN, 256>>>(p_xh, b1, p_h, 1);

    // ---- GAT layer 2: x = relu(gat(h)); gate -> h ----
    run_gemm(p_h, W2, p_xh, NN, 512, FG, nullptr, 0, false, false);
    attn_kernel<<<(NN * 2 + 3) / 4, 128>>>(p_xh, as2, ad2);
    softmax_kernel<<<(NN + 7) / 8, 256>>>();
    gat_aggregate_kernel<<<NN, 256>>>(p_xh, b2, p_x, 1);
    run_gemm(p_x, fc1_w, p_g, NN, 256, 256, fc1_b, 0, true, false);
    run_gemm(p_h, fc2_w, p_g, NN, 256, 256, fc2_b, 0, true, true);
    gate_kernel<<<(int)(((size_t)NN * 256 + 255) / 256), 256>>>(p_x, p_h, p_g, mol_bias);

    // ---- GAT layer 3: x = gat(h) (no relu); gate -> h ----
    run_gemm(p_h, W3, p_xh, NN, 512, FG, nullptr, 0, false, false);
    attn_kernel<<<(NN * 2 + 3) / 4, 128>>>(p_xh, as3, ad3);
    softmax_kernel<<<(NN + 7) / 8, 256>>>();
    gat_aggregate_kernel<<<NN, 256>>>(p_xh, b3, p_x, 0);
    run_gemm(p_x, fc1_w, p_g, NN, 256, 256, fc1_b, 0, true, false);
    run_gemm(p_h, fc2_w, p_g, NN, 256, 256, fc2_b, 0, true, true);
    gate_kernel<<<(int)(((size_t)NN * 256 + 255) / 256), 256>>>(p_x, p_h, p_g, mol_bias);

    // ---- hypergraph branch ----
    concat_kernel<<<(int)(((size_t)NN * 334 + 255) / 256), 256>>>(p_h, mol_x, p_hx);
    // layer 1: relu(Dinv * seg(Binv * seg(xt)) + hb1)
    run_gemm(p_hx, theta1, p_xt, NN, FH, 334, nullptr, 0, false, false);
    hyper_gather_kernel<<<NN, 128>>>(p_xt, p_ef, nullptr, 0, 0);
    hyper_gather_kernel<<<NN, 128>>>(p_ef, p_hy, hb1, 1, 1);
    // layer 2
    run_gemm(p_hy, theta2, p_xt, NN, FH, FH, nullptr, 0, false, false);
    hyper_gather_kernel<<<NN, 128>>>(p_xt, p_ef, nullptr, 0, 0);
    hyper_gather_kernel<<<NN, 128>>>(p_ef, p_hy, hb2, 1, 1);

    // ---- output: [h | hy] ----
    output_kernel<<<(int)(((size_t)NN * 384 + 255) / 256), 256>>>(p_h, p_hy, (float*)d_out);
}

// round 2
// speedup vs baseline: 1.8398x; 1.8398x over previous
#include <cuda_runtime.h>
#include <math.h>
#include <stdint.h>

#define NN 100000
#define EE 3200000
#define EA (EE + NN)
#define FIN 78
#define FG 256
#define FH 128

// ---------------- scratch (device globals; no allocation) ----------------
__device__ float d_xh[(size_t)NN * 512];
__device__ float d_h [(size_t)NN * 256];
__device__ float d_x [(size_t)NN * 256];
__device__ float d_g [(size_t)NN * 256];
__device__ float d_xt[(size_t)NN * 128];
__device__ float d_ef[(size_t)NN * 128];
__device__ float d_hy[(size_t)NN * 128];
__device__ float d_bc[512 * 256];
__device__ float d_cb[256];
__device__ float d_asrc[NN * 2];
__device__ float d_adst[NN * 2];
__device__ float2 d_alpha[EA];
__device__ int csrA_off[NN + 1]; __device__ int csrA_val[EA];
__device__ int csrB_off[NN + 1]; __device__ int csrB_val[EE];
__device__ int csrC_off[NN + 1]; __device__ int csrC_val[EE];
__device__ int cntA[NN], cntB[NN], cntC[NN];
__device__ int curA[NN], curB[NN], curC[NN];
__device__ float d_binv[NN], d_dinv[NN];

// ---------------- CSR construction ----------------
__global__ void zero_counts_kernel() {
    int i = blockIdx.x * blockDim.x + threadIdx.x;
    if (i < NN) { cntA[i] = 0; cntB[i] = 0; cntC[i] = 0; }
}

__global__ void count_kernel(const int* __restrict__ ei) {
    int i = blockIdx.x * blockDim.x + threadIdx.x;
    if (i >= EA) return;
    if (i < EE) {
        int s = ei[i];
        int d = ei[EE + i];
        atomicAdd(&cntA[d], 1);
        atomicAdd(&cntB[d], 1);
        atomicAdd(&cntC[s], 1);
    } else {
        atomicAdd(&cntA[i - EE], 1);  // self loop
    }
}

// 3 blocks: each does one exclusive scan (cntA->csrA_off, cntB->csrB_off, cntC->csrC_off)
__global__ void scan3_kernel() {
    const int* in; int* out;
    if (blockIdx.x == 0)      { in = cntA; out = csrA_off; }
    else if (blockIdx.x == 1) { in = cntB; out = csrB_off; }
    else                      { in = cntC; out = csrC_off; }
    const int n = NN;
    __shared__ int wsum[32];
    __shared__ int carry;
    int tid = threadIdx.x, lane = tid & 31, wid = tid >> 5;
    if (tid == 0) carry = 0;
    __syncthreads();
    for (int base = 0; base < n; base += 1024) {
        int i = base + tid;
        int v = (i < n) ? in[i] : 0;
        int x = v;
        #pragma unroll
        for (int d = 1; d < 32; d <<= 1) {
            int y = __shfl_up_sync(0xFFFFFFFFu, x, d);
            if (lane >= d) x += y;
        }
        if (lane == 31) wsum[wid] = x;
        __syncthreads();
        if (wid == 0) {
            int w = wsum[lane];
            #pragma unroll
            for (int d = 1; d < 32; d <<= 1) {
                int y = __shfl_up_sync(0xFFFFFFFFu, w, d);
                if (lane >= d) w += y;
            }
            wsum[lane] = w;
        }
        __syncthreads();
        int excl = carry + (wid ? wsum[wid - 1] : 0) + x - v;
        if (i < n) out[i] = excl;
        if (i == n - 1) out[n] = excl + v;
        __syncthreads();
        if (tid == 0) carry += wsum[31];
        __syncthreads();
    }
}

__global__ void prep_kernel() {
    int i = blockIdx.x * blockDim.x + threadIdx.x;
    if (i >= NN) return;
    curA[i] = csrA_off[i];
    curB[i] = csrB_off[i];
    curC[i] = csrC_off[i];
    d_binv[i] = cntB[i] > 0 ? 1.0f / (float)cntB[i] : 0.0f;
    d_dinv[i] = cntC[i] > 0 ? 1.0f / (float)cntC[i] : 0.0f;
}

__global__ void fill_kernel(const int* __restrict__ ei) {
    int i = blockIdx.x * blockDim.x + threadIdx.x;
    if (i >= EA) return;
    if (i < EE) {
        int s = ei[i];
        int d = ei[EE + i];
        csrA_val[atomicAdd(&curA[d], 1)] = s;
        csrB_val[atomicAdd(&curB[d], 1)] = s;
        csrC_val[atomicAdd(&curC[s], 1)] = d;
    } else {
        int n = i - EE;
        csrA_val[atomicAdd(&curA[n], 1)] = n;
    }
}

// ---------------- TF32 tensor-core GEMM ----------------
// C[M,N] = concat(A,A2)[M,Ktot] @ B[Ktot,N] (+bias, relu). 128x128x32 tiles.
__device__ __forceinline__ uint32_t f2tf32(float f) {
    uint32_t u;
    asm("cvt.rna.tf32.f32 %0, %1;" : "=r"(u) : "f"(f));
    return u;
}

__device__ __forceinline__ void mma_tf32(float* c, const uint32_t* a, uint32_t b0, uint32_t b1) {
    asm volatile(
        "mma.sync.aligned.m16n8k8.row.col.f32.tf32.tf32.f32 "
        "{%0,%1,%2,%3},{%4,%5,%6,%7},{%8,%9},{%0,%1,%2,%3};"
        : "+f"(c[0]), "+f"(c[1]), "+f"(c[2]), "+f"(c[3])
        : "r"(a[0]), "r"(a[1]), "r"(a[2]), "r"(a[3]), "r"(b0), "r"(b1));
}

template <bool VECA>
__global__ __launch_bounds__(256) void gemm_tf32_kernel(
    const float* __restrict__ A, int lda, int K1,
    const float* __restrict__ A2, int lda2,
    const float* __restrict__ B, int ldb,
    float* __restrict__ C, int M, int N, int Ktot,
    const float* __restrict__ bias, int relu)
{
    __shared__ uint32_t As[128 * 36];   // [row][k], pitch 36
    __shared__ uint32_t Bs[32 * 136];   // [k][n], pitch 136
    int tid = threadIdx.x;
    int lane = tid & 31, wid = tid >> 5;
    int wm = wid & 3, wn = wid >> 2;       // 4 m-warps x 2 n-warps
    int row0 = blockIdx.y * 128, col0 = blockIdx.x * 128;
    int g = lane >> 2, tg = lane & 3;

    float acc[2][8][4];
    #pragma unroll
    for (int mi = 0; mi < 2; mi++)
        #pragma unroll
        for (int ni = 0; ni < 8; ni++)
            #pragma unroll
            for (int q = 0; q < 4; q++) acc[mi][ni][q] = 0.0f;

    for (int k0 = 0; k0 < Ktot; k0 += 32) {
        // load A tile (128 rows x 32 k)
        #pragma unroll
        for (int i = 0; i < 4; i++) {
            int l4 = tid + i * 256;
            int r = l4 >> 3, c4 = (l4 & 7) << 2;
            int grow = row0 + r, gk = k0 + c4;
            float4 v = make_float4(0.f, 0.f, 0.f, 0.f);
            if (grow < M) {
                if (VECA && gk + 3 < K1) {
                    v = *(const float4*)(A + (size_t)grow * lda + gk);
                } else {
                    float* pv = &v.x;
                    #pragma unroll
                    for (int j = 0; j < 4; j++) {
                        int kk = gk + j;
                        float x = 0.0f;
                        if (kk < K1) x = A[(size_t)grow * lda + kk];
                        else if (kk < Ktot) x = A2[(size_t)grow * lda2 + (kk - K1)];
                        pv[j] = x;
                    }
                }
            }
            As[r * 36 + c4 + 0] = f2tf32(v.x);
            As[r * 36 + c4 + 1] = f2tf32(v.y);
            As[r * 36 + c4 + 2] = f2tf32(v.z);
            As[r * 36 + c4 + 3] = f2tf32(v.w);
        }
        // load B tile (32 k x 128 n)
        #pragma unroll
        for (int i = 0; i < 4; i++) {
            int l4 = tid + i * 256;
            int k = l4 >> 5, n4 = (l4 & 31) << 2;
            int gk = k0 + k;
            float4 v = make_float4(0.f, 0.f, 0.f, 0.f);
            if (gk < Ktot) v = *(const float4*)(B + (size_t)gk * ldb + col0 + n4);
            Bs[k * 136 + n4 + 0] = f2tf32(v.x);
            Bs[k * 136 + n4 + 1] = f2tf32(v.y);
            Bs[k * 136 + n4 + 2] = f2tf32(v.z);
            Bs[k * 136 + n4 + 3] = f2tf32(v.w);
        }
        __syncthreads();
        #pragma unroll
        for (int ks = 0; ks < 4; ks++) {
            uint32_t af[2][4];
            #pragma unroll
            for (int mi = 0; mi < 2; mi++) {
                int r = wm * 32 + mi * 16 + g;
                int c = ks * 8 + tg;
                af[mi][0] = As[r * 36 + c];
                af[mi][1] = As[(r + 8) * 36 + c];
                af[mi][2] = As[r * 36 + c + 4];
                af[mi][3] = As[(r + 8) * 36 + c + 4];
            }
            #pragma unroll
            for (int ni = 0; ni < 8; ni++) {
                int n = wn * 64 + ni * 8 + g;
                int kk = ks * 8 + tg;
                uint32_t b0 = Bs[kk * 136 + n];
                uint32_t b1 = Bs[(kk + 4) * 136 + n];
                mma_tf32(acc[0][ni], af[0], b0, b1);
                mma_tf32(acc[1][ni], af[1], b0, b1);
            }
        }
        __syncthreads();
    }
    // epilogue
    #pragma unroll
    for (int mi = 0; mi < 2; mi++) {
        int r0 = row0 + wm * 32 + mi * 16 + g;
        #pragma unroll
        for (int ni = 0; ni < 8; ni++) {
            int c = col0 + wn * 64 + ni * 8 + tg * 2;
            float b0v = bias ? bias[c] : 0.0f;
            float b1v = bias ? bias[c + 1] : 0.0f;
            float v0 = acc[mi][ni][0] + b0v;
            float v1 = acc[mi][ni][1] + b1v;
            float v2 = acc[mi][ni][2] + b0v;
            float v3 = acc[mi][ni][3] + b1v;
            if (relu) {
                v0 = fmaxf(v0, 0.f); v1 = fmaxf(v1, 0.f);
                v2 = fmaxf(v2, 0.f); v3 = fmaxf(v3, 0.f);
            }
            if (r0 < M) *(float2*)(C + (size_t)r0 * N + c) = make_float2(v0, v1);
            if (r0 + 8 < M) *(float2*)(C + (size_t)(r0 + 8) * N + c) = make_float2(v2, v3);
        }
    }
}

static void run_gemm_tf(const float* A, int lda, int K1, const float* A2, int lda2,
                        const float* B, int ldb, float* C, int M, int N, int Ktot,
                        const float* bias, int relu, bool veca) {
    dim3 grid(N / 128, (M + 127) / 128);
    if (veca)
        gemm_tf32_kernel<true><<<grid, 256>>>(A, lda, K1, A2, lda2, B, ldb, C, M, N, Ktot, bias, relu);
    else
        gemm_tf32_kernel<false><<<grid, 256>>>(A, lda, K1, A2, lda2, B, ldb, C, M, N, Ktot, bias, relu);
}

// build fused gate weight Bc[512][256] = [fc1^T ; fc2^T] and combined bias
__global__ void build_bc_kernel(const float* __restrict__ fc1w, const float* __restrict__ fc2w,
                                const float* __restrict__ fc1b, const float* __restrict__ fc2b) {
    int idx = blockIdx.x * blockDim.x + threadIdx.x;
    if (idx >= 512 * 256) return;
    int k = idx >> 8, n = idx & 255;
    d_bc[idx] = (k < 256) ? fc1w[n * 256 + k] : fc2w[n * 256 + (k - 256)];
    if (idx < 256) d_cb[idx] = fc1b[idx] + fc2b[idx];
}

// ---------------- GAT pieces ----------------
__global__ void attn_kernel(const float* __restrict__ xh,
                            const float* __restrict__ a_s,
                            const float* __restrict__ a_d) {
    int warp = threadIdx.x >> 5, lane = threadIdx.x & 31;
    int idx = blockIdx.x * 4 + warp;
    if (idx >= NN * 2) return;
    int n = idx >> 1, h = idx & 1;
    const float* row = xh + (size_t)n * 512 + h * 256;
    const float* as = a_s + h * 256;
    const float* ad = a_d + h * 256;
    float s1 = 0.0f, s2 = 0.0f;
    #pragma unroll
    for (int c = lane; c < 256; c += 32) {
        float v = row[c];
        s1 += v * as[c];
        s2 += v * ad[c];
    }
    #pragma unroll
    for (int d = 16; d; d >>= 1) {
        s1 += __shfl_down_sync(0xFFFFFFFFu, s1, d);
        s2 += __shfl_down_sync(0xFFFFFFFFu, s2, d);
    }
    if (lane == 0) { d_asrc[idx] = s1; d_adst[idx] = s2; }
}

__device__ __forceinline__ float lrelu02(float v) { return v >= 0.0f ? v : 0.2f * v; }

__global__ void softmax_kernel() {
    int n = blockIdx.x * (blockDim.x >> 5) + (threadIdx.x >> 5);
    int lane = threadIdx.x & 31;
    if (n >= NN) return;
    int s0 = csrA_off[n], s1 = csrA_off[n + 1];
    float ad0 = d_adst[n * 2], ad1 = d_adst[n * 2 + 1];
    float m0 = -1e30f, m1 = -1e30f;
    for (int p = s0 + lane; p < s1; p += 32) {
        int src = csrA_val[p];
        float e0 = lrelu02(d_asrc[src * 2] + ad0);
        float e1 = lrelu02(d_asrc[src * 2 + 1] + ad1);
        m0 = fmaxf(m0, e0); m1 = fmaxf(m1, e1);
    }
    #pragma unroll
    for (int d = 16; d; d >>= 1) {
        m0 = fmaxf(m0, __shfl_xor_sync(0xFFFFFFFFu, m0, d));
        m1 = fmaxf(m1, __shfl_xor_sync(0xFFFFFFFFu, m1, d));
    }
    float sum0 = 0.0f, sum1 = 0.0f;
    for (int p = s0 + lane; p < s1; p += 32) {
        int src = csrA_val[p];
        float e0 = lrelu02(d_asrc[src * 2] + ad0);
        float e1 = lrelu02(d_asrc[src * 2 + 1] + ad1);
        float x0 = __expf(e0 - m0), x1 = __expf(e1 - m1);
        d_alpha[p] = make_float2(x0, x1);
        sum0 += x0; sum1 += x1;
    }
    #pragma unroll
    for (int d = 16; d; d >>= 1) {
        sum0 += __shfl_xor_sync(0xFFFFFFFFu, sum0, d);
        sum1 += __shfl_xor_sync(0xFFFFFFFFu, sum1, d);
    }
    float r0 = 1.0f / sum0, r1 = 1.0f / sum1;
    for (int p = s0 + lane; p < s1; p += 32) {
        float2 a = d_alpha[p];
        a.x *= r0; a.y *= r1;
        d_alpha[p] = a;
    }
}

__global__ void gat_aggregate_kernel(const float* __restrict__ xh,
                                     const float* __restrict__ bias,
                                     float* __restrict__ out, int relu) {
    int n = blockIdx.x;
    int t = threadIdx.x;
    int s0 = csrA_off[n], s1 = csrA_off[n + 1];
    float acc0 = 0.0f, acc1 = 0.0f;
    __shared__ int ssrc[256];
    __shared__ float2 salp[256];
    for (int base = s0; base < s1; base += 256) {
        int cnt = min(256, s1 - base);
        __syncthreads();
        if (t < cnt) { ssrc[t] = csrA_val[base + t]; salp[t] = d_alpha[base + t]; }
        __syncthreads();
        #pragma unroll 4
        for (int j = 0; j < cnt; j++) {
            int s = ssrc[j];
            float2 a = salp[j];
            const float* row = xh + (size_t)s * 512;
            acc0 += a.x * row[t];
            acc1 += a.y * row[256 + t];
        }
    }
    float v = 0.5f * (acc0 + acc1) + bias[t];
    if (relu) v = fmaxf(v, 0.0f);
    out[(size_t)n * 256 + t] = v;
}

// h = z*x + (1-z)*h,  z = sigmoid(G + mol_bias)   (G already has fc biases)
__global__ void gate_kernel(const float* __restrict__ x, float* __restrict__ h,
                            const float* __restrict__ G, const float* __restrict__ mol_bias) {
    size_t i = (size_t)blockIdx.x * blockDim.x + threadIdx.x;
    if (i >= (size_t)NN * 256) return;
    int col = (int)(i & 255);
    float v = G[i] + mol_bias[col];
    float z = 1.0f / (1.0f + __expf(-v));
    h[i] = z * x[i] + (1.0f - z) * h[i];
}

// ---------------- hypergraph ----------------
__global__ void hyper_gather_kernel(const float* __restrict__ in, float* __restrict__ out,
                                    const float* __restrict__ bias, int which, int relu) {
    const int* off = which ? csrC_off : csrB_off;
    const int* val = which ? csrC_val : csrB_val;
    const float* inv = which ? d_dinv : d_binv;
    int n = blockIdx.x;
    int t = threadIdx.x;
    int s0 = off[n], s1 = off[n + 1];
    float acc = 0.0f;
    __shared__ int sv[128];
    for (int base = s0; base < s1; base += 128) {
        int cnt = min(128, s1 - base);
        __syncthreads();
        if (t < cnt) sv[t] = val[base + t];
        __syncthreads();
        #pragma unroll 4
        for (int j = 0; j < cnt; j++)
            acc += in[(size_t)sv[j] * FH + t];
    }
    float v = acc * inv[n];
    if (bias) v += bias[t];
    if (relu) v = fmaxf(v, 0.0f);
    out[(size_t)n * FH + t] = v;
}

__global__ void output_kernel(const float* __restrict__ h, const float* __restrict__ hy,
                              float* __restrict__ out) {
    size_t i = (size_t)blockIdx.x * blockDim.x + threadIdx.x;
    if (i >= (size_t)NN * 384) return;
    int n = (int)(i / 384);
    int c = (int)(i % 384);
    out[i] = (c < 256) ? h[(size_t)n * 256 + c] : hy[(size_t)n * FH + (c - 256)];
}

// ---------------- host side ----------------
extern "C" void kernel_launch(void* const* d_in, const int* in_sizes, int n_in,
                              void* d_out, int out_size) {
    const float* mol_x = (const float*)d_in[0];
    const int*   ei    = (const int*)d_in[1];
    const float* W1 = (const float*)d_in[3];
    const float* as1 = (const float*)d_in[4];
    const float* ad1 = (const float*)d_in[5];
    const float* b1 = (const float*)d_in[6];
    const float* W2 = (const float*)d_in[7];
    const float* as2 = (const float*)d_in[8];
    const float* ad2 = (const float*)d_in[9];
    const float* b2 = (const float*)d_in[10];
    const float* W3 = (const float*)d_in[11];
    const float* as3 = (const float*)d_in[12];
    const float* ad3 = (const float*)d_in[13];
    const float* b3 = (const float*)d_in[14];
    const float* fc1_w = (const float*)d_in[15];
    const float* fc1_b = (const float*)d_in[16];
    const float* fc2_w = (const float*)d_in[17];
    const float* fc2_b = (const float*)d_in[18];
    const float* mol_bias = (const float*)d_in[19];
    const float* theta1 = (const float*)d_in[20];
    const float* hb1 = (const float*)d_in[21];
    const float* theta2 = (const float*)d_in[22];
    const float* hb2 = (const float*)d_in[23];

    float *p_xh, *p_h, *p_x, *p_g, *p_xt, *p_ef, *p_hy, *p_bc, *p_cb;
    cudaGetSymbolAddress((void**)&p_xh, d_xh);
    cudaGetSymbolAddress((void**)&p_h, d_h);
    cudaGetSymbolAddress((void**)&p_x, d_x);
    cudaGetSymbolAddress((void**)&p_g, d_g);
    cudaGetSymbolAddress((void**)&p_xt, d_xt);
    cudaGetSymbolAddress((void**)&p_ef, d_ef);
    cudaGetSymbolAddress((void**)&p_hy, d_hy);
    cudaGetSymbolAddress((void**)&p_bc, d_bc);
    cudaGetSymbolAddress((void**)&p_cb, d_cb);

    // ---- CSR build (launches 1..5) ----
    zero_counts_kernel<<<(NN + 255) / 256, 256>>>();
    count_kernel<<<(EA + 255) / 256, 256>>>(ei);
    scan3_kernel<<<3, 1024>>>();
    prep_kernel<<<(NN + 255) / 256, 256>>>();
    fill_kernel<<<(EA + 255) / 256, 256>>>(ei);

    // ---- GAT layer 1: h = relu(gat(mol_x)) ----  (gemm is launch #6 -> profiled)
    run_gemm_tf(mol_x, FIN, FIN, nullptr, 0, W1, 512, p_xh, NN, 512, FIN, nullptr, 0, false);
    attn_kernel<<<(NN * 2 + 3) / 4, 128>>>(p_xh, as1, ad1);
    softmax_kernel<<<(NN + 7) / 8, 256>>>();
    gat_aggregate_kernel<<<NN, 256>>>(p_xh, b1, p_h, 1);

    // fused gate weights (once)
    build_bc_kernel<<<(512 * 256 + 255) / 256, 256>>>(fc1_w, fc2_w, fc1_b, fc2_b);

    // ---- GAT layer 2: x = relu(gat(h)); gate -> h ----
    run_gemm_tf(p_h, 256, 256, nullptr, 0, W2, 512, p_xh, NN, 512, 256, nullptr, 0, true);
    attn_kernel<<<(NN * 2 + 3) / 4, 128>>>(p_xh, as2, ad2);
    softmax_kernel<<<(NN + 7) / 8, 256>>>();
    gat_aggregate_kernel<<<NN, 256>>>(p_xh, b2, p_x, 1);
    // G = [x|h] @ Bc + cb
    run_gemm_tf(p_x, 256, 256, p_h, 256, p_bc, 256, p_g, NN, 256, 512, p_cb, 0, true);
    gate_kernel<<<(int)(((size_t)NN * 256 + 255) / 256), 256>>>(p_x, p_h, p_g, mol_bias);

    // ---- GAT layer 3: x = gat(h) (no relu); gate -> h ----
    run_gemm_tf(p_h, 256, 256, nullptr, 0, W3, 512, p_xh, NN, 512, 256, nullptr, 0, true);
    attn_kernel<<<(NN * 2 + 3) / 4, 128>>>(p_xh, as3, ad3);
    softmax_kernel<<<(NN + 7) / 8, 256>>>();
    gat_aggregate_kernel<<<NN, 256>>>(p_xh, b3, p_x, 0);
    run_gemm_tf(p_x, 256, 256, p_h, 256, p_bc, 256, p_g, NN, 256, 512, p_cb, 0, true);
    gate_kernel<<<(int)(((size_t)NN * 256 + 255) / 256), 256>>>(p_x, p_h, p_g, mol_bias);

    // ---- hypergraph branch ----
    // xt = [h | mol_x] @ theta1   (K = 334, split 256 + 78)
    run_gemm_tf(p_h, 256, 256, mol_x, FIN, theta1, 128, p_xt, NN, 128, 334, nullptr, 0, true);
    hyper_gather_kernel<<<NN, 128>>>(p_xt, p_ef, nullptr, 0, 0);
    hyper_gather_kernel<<<NN, 128>>>(p_ef, p_hy, hb1, 1, 1);
    run_gemm_tf(p_hy, 128, 128, nullptr, 0, theta2, 128, p_xt, NN, 128, 128, nullptr, 0, true);
    hyper_gather_kernel<<<NN, 128>>>(p_xt, p_ef, nullptr, 0, 0);
    hyper_gather_kernel<<<NN, 128>>>(p_ef, p_hy, hb2, 1, 1);

    // ---- output: [h | hy] ----
    output_kernel<<<(int)(((size_t)NN * 384 + 255) / 256), 256>>>(p_h, p_hy, (float*)d_out);
}

// round 3
// speedup vs baseline: 3.0789x; 1.6735x over previous
#include <cuda_runtime.h>
#include <cuda_fp16.h>
#include <math.h>
#include <stdint.h>

#define NN 100000
#define EE 3200000
#define EA (EE + NN)
#define FIN 78
#define FG 256
#define FH 128

// ---------------- scratch (device globals; no allocation) ----------------
__device__ __half d_xh[(size_t)NN * 512];
__device__ float d_h [(size_t)NN * 256];
__device__ float d_x [(size_t)NN * 256];
__device__ float d_g [(size_t)NN * 256];
__device__ __half d_xt[(size_t)NN * 128];
__device__ __half d_ef[(size_t)NN * 128];
__device__ float d_hy[(size_t)NN * 128];
__device__ float d_bc[512 * 256];
__device__ float d_cb[256];
__device__ float d_wv[256 * 4];
__device__ float d_asrc[NN * 2];
__device__ float d_adst[NN * 2];
__device__ float2 d_alpha[EA];
__device__ int csrA_off[NN + 1]; __device__ int csrA_val[EA];
__device__ int csrB_off[NN + 1]; __device__ int csrB_val[EE];
__device__ int csrC_off[NN + 1]; __device__ int csrC_val[EE];
__device__ int cntA[NN], cntB[NN], cntC[NN];
__device__ int curA[NN], curB[NN], curC[NN];
__device__ float d_binv[NN], d_dinv[NN];

// ---------------- CSR construction ----------------
__global__ void zero_counts_kernel() {
    int i = blockIdx.x * blockDim.x + threadIdx.x;
    if (i < NN) { cntA[i] = 0; cntB[i] = 0; cntC[i] = 0; }
}

__global__ void count_kernel(const int* __restrict__ ei) {
    int i = blockIdx.x * blockDim.x + threadIdx.x;
    if (i >= EA) return;
    if (i < EE) {
        int s = ei[i];
        int d = ei[EE + i];
        atomicAdd(&cntA[d], 1);
        atomicAdd(&cntB[d], 1);
        atomicAdd(&cntC[s], 1);
    } else {
        atomicAdd(&cntA[i - EE], 1);  // self loop
    }
}

__global__ void scan3_kernel() {
    const int* in; int* out;
    if (blockIdx.x == 0)      { in = cntA; out = csrA_off; }
    else if (blockIdx.x == 1) { in = cntB; out = csrB_off; }
    else                      { in = cntC; out = csrC_off; }
    const int n = NN;
    __shared__ int wsum[32];
    __shared__ int carry;
    int tid = threadIdx.x, lane = tid & 31, wid = tid >> 5;
    if (tid == 0) carry = 0;
    __syncthreads();
    for (int base = 0; base < n; base += 1024) {
        int i = base + tid;
        int v = (i < n) ? in[i] : 0;
        int x = v;
        #pragma unroll
        for (int d = 1; d < 32; d <<= 1) {
            int y = __shfl_up_sync(0xFFFFFFFFu, x, d);
            if (lane >= d) x += y;
        }
        if (lane == 31) wsum[wid] = x;
        __syncthreads();
        if (wid == 0) {
            int w = wsum[lane];
            #pragma unroll
            for (int d = 1; d < 32; d <<= 1) {
                int y = __shfl_up_sync(0xFFFFFFFFu, w, d);
                if (lane >= d) w += y;
            }
            wsum[lane] = w;
        }
        __syncthreads();
        int excl = carry + (wid ? wsum[wid - 1] : 0) + x - v;
        if (i < n) out[i] = excl;
        if (i == n - 1) out[n] = excl + v;
        __syncthreads();
        if (tid == 0) carry += wsum[31];
        __syncthreads();
    }
}

__global__ void prep_kernel() {
    int i = blockIdx.x * blockDim.x + threadIdx.x;
    if (i >= NN) return;
    curA[i] = csrA_off[i];
    curB[i] = csrB_off[i];
    curC[i] = csrC_off[i];
    d_binv[i] = cntB[i] > 0 ? 1.0f / (float)cntB[i] : 0.0f;
    d_dinv[i] = cntC[i] > 0 ? 1.0f / (float)cntC[i] : 0.0f;
}

__global__ void fill_kernel(const int* __restrict__ ei) {
    int i = blockIdx.x * blockDim.x + threadIdx.x;
    if (i >= EA) return;
    if (i < EE) {
        int s = ei[i];
        int d = ei[EE + i];
        csrA_val[atomicAdd(&curA[d], 1)] = s;
        csrB_val[atomicAdd(&curB[d], 1)] = s;
        csrC_val[atomicAdd(&curC[s], 1)] = d;
    } else {
        int n = i - EE;
        csrA_val[atomicAdd(&curA[n], 1)] = n;
    }
}

// ---------------- TF32 tensor-core GEMM (pipelined) ----------------
__device__ __forceinline__ uint32_t f2tf32(float f) {
    uint32_t u;
    asm("cvt.rna.tf32.f32 %0, %1;" : "=r"(u) : "f"(f));
    return u;
}

__device__ __forceinline__ void mma_tf32(float* c, const uint32_t* a, uint32_t b0, uint32_t b1) {
    asm volatile(
        "mma.sync.aligned.m16n8k8.row.col.f32.tf32.tf32.f32 "
        "{%0,%1,%2,%3},{%4,%5,%6,%7},{%8,%9},{%0,%1,%2,%3};"
        : "+f"(c[0]), "+f"(c[1]), "+f"(c[2]), "+f"(c[3])
        : "r"(a[0]), "r"(a[1]), "r"(a[2]), "r"(a[3]), "r"(b0), "r"(b1));
}

#define ASTR (128 * 36)
#define BSTR (32 * 136)

template <bool VECA>
__device__ __forceinline__ void g_loadA(float4* ra, const float* A, int lda, int K1,
                                        const float* A2, int lda2, int Ktot, int M,
                                        int row0, int k0, int tid) {
    #pragma unroll
    for (int i = 0; i < 4; i++) {
        int l4 = tid + i * 256;
        int r = l4 >> 3, c4 = (l4 & 7) << 2;
        int grow = row0 + r, gk = k0 + c4;
        float4 v = make_float4(0.f, 0.f, 0.f, 0.f);
        if (grow < M) {
            if (VECA && gk + 3 < K1) {
                v = *(const float4*)(A + (size_t)grow * lda + gk);
            } else {
                float* pv = &v.x;
                #pragma unroll
                for (int j = 0; j < 4; j++) {
                    int kk = gk + j;
                    float x = 0.0f;
                    if (kk < K1) x = A[(size_t)grow * lda + kk];
                    else if (kk < Ktot) x = A2[(size_t)grow * lda2 + (kk - K1)];
                    pv[j] = x;
                }
            }
        }
        ra[i] = v;
    }
}

__device__ __forceinline__ void g_loadB(float4* rb, const float* B, int ldb, int col0,
                                        int Ktot, int k0, int tid) {
    #pragma unroll
    for (int i = 0; i < 4; i++) {
        int l4 = tid + i * 256;
        int k = l4 >> 5, n4 = (l4 & 31) << 2;
        int gk = k0 + k;
        float4 v = make_float4(0.f, 0.f, 0.f, 0.f);
        if (gk < Ktot) v = *(const float4*)(B + (size_t)gk * ldb + col0 + n4);
        rb[i] = v;
    }
}

__device__ __forceinline__ void g_storeA(const float4* ra, uint32_t* As, int tid) {
    #pragma unroll
    for (int i = 0; i < 4; i++) {
        int l4 = tid + i * 256;
        int r = l4 >> 3, c4 = (l4 & 7) << 2;
        As[r * 36 + c4 + 0] = f2tf32(ra[i].x);
        As[r * 36 + c4 + 1] = f2tf32(ra[i].y);
        As[r * 36 + c4 + 2] = f2tf32(ra[i].z);
        As[r * 36 + c4 + 3] = f2tf32(ra[i].w);
    }
}

__device__ __forceinline__ void g_storeB(const float4* rb, uint32_t* Bs, int tid) {
    #pragma unroll
    for (int i = 0; i < 4; i++) {
        int l4 = tid + i * 256;
        int k = l4 >> 5, n4 = (l4 & 31) << 2;
        Bs[k * 136 + n4 + 0] = f2tf32(rb[i].x);
        Bs[k * 136 + n4 + 1] = f2tf32(rb[i].y);
        Bs[k * 136 + n4 + 2] = f2tf32(rb[i].z);
        Bs[k * 136 + n4 + 3] = f2tf32(rb[i].w);
    }
}

// EPI: 0 = float out (+bias,relu), 1 = half out, 2 = gate blend (writes float h_new)
template <bool VECA, int EPI>
__global__ __launch_bounds__(256) void gemm_tf32_kernel(
    const float* __restrict__ A, int lda, int K1,
    const float* __restrict__ A2, int lda2,
    const float* __restrict__ B, int ldb,
    void* __restrict__ Cout, int M, int N, int Ktot,
    const float* __restrict__ bias, int relu, const float* __restrict__ molb)
{
    extern __shared__ uint32_t sm[];
    uint32_t* Asm = sm;                 // 2 * ASTR
    uint32_t* Bsm = sm + 2 * ASTR;      // 2 * BSTR
    int tid = threadIdx.x;
    int lane = tid & 31, wid = tid >> 5;
    int wm = wid & 3, wn = wid >> 2;
    int row0 = blockIdx.y * 128, col0 = blockIdx.x * 128;
    int g = lane >> 2, tg = lane & 3;

    float acc[2][8][4];
    #pragma unroll
    for (int mi = 0; mi < 2; mi++)
        #pragma unroll
        for (int ni = 0; ni < 8; ni++)
            #pragma unroll
            for (int q = 0; q < 4; q++) acc[mi][ni][q] = 0.0f;

    int T = (Ktot + 31) >> 5;
    float4 ra[4], rb[4];
    g_loadA<VECA>(ra, A, lda, K1, A2, lda2, Ktot, M, row0, 0, tid);
    g_loadB(rb, B, ldb, col0, Ktot, 0, tid);
    g_storeA(ra, Asm, tid);
    g_storeB(rb, Bsm, tid);
    __syncthreads();

    for (int t = 0; t < T; t++) {
        int buf = t & 1;
        bool more = (t + 1 < T);
        if (more) {
            g_loadA<VECA>(ra, A, lda, K1, A2, lda2, Ktot, M, row0, (t + 1) << 5, tid);
            g_loadB(rb, B, ldb, col0, Ktot, (t + 1) << 5, tid);
        }
        const uint32_t* As = Asm + buf * ASTR;
        const uint32_t* Bs = Bsm + buf * BSTR;
        #pragma unroll
        for (int ks = 0; ks < 4; ks++) {
            uint32_t af[2][4];
            #pragma unroll
            for (int mi = 0; mi < 2; mi++) {
                int r = wm * 32 + mi * 16 + g;
                int c = ks * 8 + tg;
                af[mi][0] = As[r * 36 + c];
                af[mi][1] = As[(r + 8) * 36 + c];
                af[mi][2] = As[r * 36 + c + 4];
                af[mi][3] = As[(r + 8) * 36 + c + 4];
            }
            #pragma unroll
            for (int ni = 0; ni < 8; ni++) {
                int n = wn * 64 + ni * 8 + g;
                int kk = ks * 8 + tg;
                uint32_t b0 = Bs[kk * 136 + n];
                uint32_t b1 = Bs[(kk + 4) * 136 + n];
                mma_tf32(acc[0][ni], af[0], b0, b1);
                mma_tf32(acc[1][ni], af[1], b0, b1);
            }
        }
        if (more) {
            g_storeA(ra, Asm + (buf ^ 1) * ASTR, tid);
            g_storeB(rb, Bsm + (buf ^ 1) * BSTR, tid);
        }
        __syncthreads();
    }

    // epilogue
    #pragma unroll
    for (int mi = 0; mi < 2; mi++) {
        int r0 = row0 + wm * 32 + mi * 16 + g;
        #pragma unroll
        for (int ni = 0; ni < 8; ni++) {
            int c = col0 + wn * 64 + ni * 8 + tg * 2;
            float v0 = acc[mi][ni][0], v1 = acc[mi][ni][1];
            float v2 = acc[mi][ni][2], v3 = acc[mi][ni][3];
            if (EPI == 0) {
                float* C = (float*)Cout;
                float b0v = bias ? bias[c] : 0.0f;
                float b1v = bias ? bias[c + 1] : 0.0f;
                v0 += b0v; v1 += b1v; v2 += b0v; v3 += b1v;
                if (relu) {
                    v0 = fmaxf(v0, 0.f); v1 = fmaxf(v1, 0.f);
                    v2 = fmaxf(v2, 0.f); v3 = fmaxf(v3, 0.f);
                }
                if (r0 < M) *(float2*)(C + (size_t)r0 * N + c) = make_float2(v0, v1);
                if (r0 + 8 < M) *(float2*)(C + (size_t)(r0 + 8) * N + c) = make_float2(v2, v3);
            } else if (EPI == 1) {
                __half* C = (__half*)Cout;
                if (r0 < M) *(__half2*)(C + (size_t)r0 * N + c) = __floats2half2_rn(v0, v1);
                if (r0 + 8 < M) *(__half2*)(C + (size_t)(r0 + 8) * N + c) = __floats2half2_rn(v2, v3);
            } else {
                float* C = (float*)Cout;
                float cb0 = bias[c] + molb[c];
                float cb1 = bias[c + 1] + molb[c + 1];
                if (r0 < M) {
                    float z0 = 1.0f / (1.0f + __expf(-(v0 + cb0)));
                    float z1 = 1.0f / (1.0f + __expf(-(v1 + cb1)));
                    float x0 = A[(size_t)r0 * lda + c], x1 = A[(size_t)r0 * lda + c + 1];
                    float h0 = A2[(size_t)r0 * lda2 + c], h1 = A2[(size_t)r0 * lda2 + c + 1];
                    *(float2*)(C + (size_t)r0 * N + c) =
                        make_float2(z0 * x0 + (1.0f - z0) * h0, z1 * x1 + (1.0f - z1) * h1);
                }
                int r1 = r0 + 8;
                if (r1 < M) {
                    float z0 = 1.0f / (1.0f + __expf(-(v2 + cb0)));
                    float z1 = 1.0f / (1.0f + __expf(-(v3 + cb1)));
                    float x0 = A[(size_t)r1 * lda + c], x1 = A[(size_t)r1 * lda + c + 1];
                    float h0 = A2[(size_t)r1 * lda2 + c], h1 = A2[(size_t)r1 * lda2 + c + 1];
                    *(float2*)(C + (size_t)r1 * N + c) =
                        make_float2(z0 * x0 + (1.0f - z0) * h0, z1 * x1 + (1.0f - z1) * h1);
                }
            }
        }
    }
}

#define GEMM_SMEM ((2 * ASTR + 2 * BSTR) * 4)

template <bool VECA, int EPI>
static void run_gemm(const float* A, int lda, int K1, const float* A2, int lda2,
                     const float* B, int ldb, void* C, int M, int N, int Ktot,
                     const float* bias, int relu, const float* molb) {
    cudaFuncSetAttribute(gemm_tf32_kernel<VECA, EPI>,
                         cudaFuncAttributeMaxDynamicSharedMemorySize, GEMM_SMEM);
    dim3 grid(N / 128, (M + 127) / 128);
    gemm_tf32_kernel<VECA, EPI><<<grid, 256, GEMM_SMEM>>>(
        A, lda, K1, A2, lda2, B, ldb, C, M, N, Ktot, bias, relu, molb);
}

// build fused gate weight Bc[512][256] = [fc1^T ; fc2^T] and combined bias
__global__ void build_bc_kernel(const float* __restrict__ fc1w, const float* __restrict__ fc2w,
                                const float* __restrict__ fc1b, const float* __restrict__ fc2b) {
    int idx = blockIdx.x * blockDim.x + threadIdx.x;
    if (idx >= 512 * 256) return;
    int k = idx >> 8, n = idx & 255;
    d_bc[idx] = (k < 256) ? fc1w[n * 256 + k] : fc2w[n * 256 + (k - 256)];
    if (idx < 256) d_cb[idx] = fc1b[idx] + fc2b[idx];
}

// ---------------- exact attention logits (independent of fp16 xh) ----------------
// wv[k][0]=sum_c W[k,c]*as[0,c]; wv[k][1]=sum_c W[k,256+c]*as[1,c]; [2],[3] same with ad
__global__ void build_wv_kernel(const float* __restrict__ W, const float* __restrict__ as,
                                const float* __restrict__ ad) {
    int k = blockIdx.x, t = threadIdx.x;  // 256 threads
    float w0 = W[(size_t)k * 512 + t], w1 = W[(size_t)k * 512 + 256 + t];
    float p0 = w0 * as[t], p1 = w1 * as[256 + t];
    float p2 = w0 * ad[t], p3 = w1 * ad[256 + t];
    __shared__ float red[8][4];
    int lane = t & 31, wid = t >> 5;
    #pragma unroll
    for (int d = 16; d; d >>= 1) {
        p0 += __shfl_down_sync(0xFFFFFFFFu, p0, d);
        p1 += __shfl_down_sync(0xFFFFFFFFu, p1, d);
        p2 += __shfl_down_sync(0xFFFFFFFFu, p2, d);
        p3 += __shfl_down_sync(0xFFFFFFFFu, p3, d);
    }
    if (lane == 0) { red[wid][0] = p0; red[wid][1] = p1; red[wid][2] = p2; red[wid][3] = p3; }
    __syncthreads();
    if (t == 0) {
        float r0 = 0, r1 = 0, r2 = 0, r3 = 0;
        #pragma unroll
        for (int w = 0; w < 8; w++) { r0 += red[w][0]; r1 += red[w][1]; r2 += red[w][2]; r3 += red[w][3]; }
        d_wv[k * 4 + 0] = r0; d_wv[k * 4 + 1] = r1; d_wv[k * 4 + 2] = r2; d_wv[k * 4 + 3] = r3;
    }
}

// a_src[n,h] = x[n,:K] . wv[:,h]; a_dst similarly (warp per node)
__global__ void attn2_kernel(const float* __restrict__ x, int K) {
    int warp = threadIdx.x >> 5, lane = threadIdx.x & 31;
    int n = blockIdx.x * 4 + warp;
    if (n >= NN) return;
    const float* xr = x + (size_t)n * K;
    float s0 = 0, s1 = 0, s2 = 0, s3 = 0;
    for (int c = lane; c < K; c += 32) {
        float xv = xr[c];
        float4 wv = ((const float4*)d_wv)[c];
        s0 += xv * wv.x; s1 += xv * wv.y; s2 += xv * wv.z; s3 += xv * wv.w;
    }
    #pragma unroll
    for (int d = 16; d; d >>= 1) {
        s0 += __shfl_down_sync(0xFFFFFFFFu, s0, d);
        s1 += __shfl_down_sync(0xFFFFFFFFu, s1, d);
        s2 += __shfl_down_sync(0xFFFFFFFFu, s2, d);
        s3 += __shfl_down_sync(0xFFFFFFFFu, s3, d);
    }
    if (lane == 0) {
        d_asrc[n * 2] = s0; d_asrc[n * 2 + 1] = s1;
        d_adst[n * 2] = s2; d_adst[n * 2 + 1] = s3;
    }
}

__device__ __forceinline__ float lrelu02(float v) { return v >= 0.0f ? v : 0.2f * v; }

__global__ void softmax_kernel() {
    int n = blockIdx.x * (blockDim.x >> 5) + (threadIdx.x >> 5);
    int lane = threadIdx.x & 31;
    if (n >= NN) return;
    int s0 = csrA_off[n], s1 = csrA_off[n + 1];
    float ad0 = d_adst[n * 2], ad1 = d_adst[n * 2 + 1];
    float m0 = -1e30f, m1 = -1e30f;
    for (int p = s0 + lane; p < s1; p += 32) {
        int src = csrA_val[p];
        float e0 = lrelu02(d_asrc[src * 2] + ad0);
        float e1 = lrelu02(d_asrc[src * 2 + 1] + ad1);
        m0 = fmaxf(m0, e0); m1 = fmaxf(m1, e1);
    }
    #pragma unroll
    for (int d = 16; d; d >>= 1) {
        m0 = fmaxf(m0, __shfl_xor_sync(0xFFFFFFFFu, m0, d));
        m1 = fmaxf(m1, __shfl_xor_sync(0xFFFFFFFFu, m1, d));
    }
    float sum0 = 0.0f, sum1 = 0.0f;
    for (int p = s0 + lane; p < s1; p += 32) {
        int src = csrA_val[p];
        float e0 = lrelu02(d_asrc[src * 2] + ad0);
        float e1 = lrelu02(d_asrc[src * 2 + 1] + ad1);
        float x0 = __expf(e0 - m0), x1 = __expf(e1 - m1);
        d_alpha[p] = make_float2(x0, x1);
        sum0 += x0; sum1 += x1;
    }
    #pragma unroll
    for (int d = 16; d; d >>= 1) {
        sum0 += __shfl_xor_sync(0xFFFFFFFFu, sum0, d);
        sum1 += __shfl_xor_sync(0xFFFFFFFFu, sum1, d);
    }
    float r0 = 1.0f / sum0, r1 = 1.0f / sum1;
    for (int p = s0 + lane; p < s1; p += 32) {
        float2 a = d_alpha[p];
        a.x *= r0; a.y *= r1;
        d_alpha[p] = a;
    }
}

// block(128) per destination node: gathers half2 rows of xh
__global__ void gat_aggregate_kernel(const __half* __restrict__ xh,
                                     const float* __restrict__ bias,
                                     float* __restrict__ out, int relu) {
    int n = blockIdx.x;
    int t = threadIdx.x;  // 128
    int s0 = csrA_off[n], s1 = csrA_off[n + 1];
    float a00 = 0, a01 = 0, a10 = 0, a11 = 0;
    __shared__ int ssrc[128];
    __shared__ float2 salp[128];
    for (int base = s0; base < s1; base += 128) {
        int cnt = min(128, s1 - base);
        __syncthreads();
        if (t < cnt) { ssrc[t] = csrA_val[base + t]; salp[t] = d_alpha[base + t]; }
        __syncthreads();
        #pragma unroll 2
        for (int j = 0; j < cnt; j++) {
            const __half2* row = (const __half2*)(xh + (size_t)ssrc[j] * 512);
            float2 a = salp[j];
            float2 f0 = __half22float2(row[t]);
            float2 f1 = __half22float2(row[128 + t]);
            a00 += a.x * f0.x; a01 += a.x * f0.y;
            a10 += a.y * f1.x; a11 += a.y * f1.y;
        }
    }
    int c = t * 2;
    float v0 = 0.5f * (a00 + a10) + bias[c];
    float v1 = 0.5f * (a01 + a11) + bias[c + 1];
    if (relu) { v0 = fmaxf(v0, 0.f); v1 = fmaxf(v1, 0.f); }
    *(float2*)(out + (size_t)n * 256 + c) = make_float2(v0, v1);
}

// ---------------- hypergraph ----------------
// 64 threads per node; in is half2 rows of 64; which=0: csrB/binv, which=1: csrC/dinv
template <bool OUTH>
__global__ void hyper_gather_kernel(const __half2* __restrict__ in, void* __restrict__ outp,
                                    const float* __restrict__ bias, int which, int relu) {
    const int* off = which ? csrC_off : csrB_off;
    const int* val = which ? csrC_val : csrB_val;
    int n = blockIdx.x;
    int t = threadIdx.x;  // 64
    int s0 = off[n], s1 = off[n + 1];
    float ax = 0, ay = 0;
    __shared__ int sv[64];
    for (int base = s0; base < s1; base += 64) {
        int cnt = min(64, s1 - base);
        __syncthreads();
        if (t < cnt) sv[t] = val[base + t];
        __syncthreads();
        #pragma unroll 4
        for (int j = 0; j < cnt; j++) {
            float2 f = __half22float2(in[(size_t)sv[j] * 64 + t]);
            ax += f.x; ay += f.y;
        }
    }
    float inv = which ? d_dinv[n] : d_binv[n];
    ax *= inv; ay *= inv;
    if (bias) { ax += bias[t * 2]; ay += bias[t * 2 + 1]; }
    if (relu) { ax = fmaxf(ax, 0.f); ay = fmaxf(ay, 0.f); }
    if (OUTH) ((__half2*)outp)[(size_t)n * 64 + t] = __floats2half2_rn(ax, ay);
    else ((float2*)outp)[(size_t)n * 64 + t] = make_float2(ax, ay);
}

__global__ void output_kernel(const float* __restrict__ h, const float* __restrict__ hy,
                              float* __restrict__ out) {
    size_t i = (size_t)blockIdx.x * blockDim.x + threadIdx.x;
    if (i >= (size_t)NN * 384) return;
    int n = (int)(i / 384);
    int c = (int)(i % 384);
    out[i] = (c < 256) ? h[(size_t)n * 256 + c] : hy[(size_t)n * FH + (c - 256)];
}

// ---------------- host side ----------------
extern "C" void kernel_launch(void* const* d_in, const int* in_sizes, int n_in,
                              void* d_out, int out_size) {
    const float* mol_x = (const float*)d_in[0];
    const int*   ei    = (const int*)d_in[1];
    const float* W1 = (const float*)d_in[3];
    const float* as1 = (const float*)d_in[4];
    const float* ad1 = (const float*)d_in[5];
    const float* b1 = (const float*)d_in[6];
    const float* W2 = (const float*)d_in[7];
    const float* as2 = (const float*)d_in[8];
    const float* ad2 = (const float*)d_in[9];
    const float* b2 = (const float*)d_in[10];
    const float* W3 = (const float*)d_in[11];
    const float* as3 = (const float*)d_in[12];
    const float* ad3 = (const float*)d_in[13];
    const float* b3 = (const float*)d_in[14];
    const float* fc1_w = (const float*)d_in[15];
    const float* fc1_b = (const float*)d_in[16];
    const float* fc2_w = (const float*)d_in[17];
    const float* fc2_b = (const float*)d_in[18];
    const float* mol_bias = (const float*)d_in[19];
    const float* theta1 = (const float*)d_in[20];
    const float* hb1 = (const float*)d_in[21];
    const float* theta2 = (const float*)d_in[22];
    const float* hb2 = (const float*)d_in[23];

    __half *p_xh, *p_xt, *p_ef;
    float *p_h, *p_x, *p_g, *p_hy, *p_bc, *p_cb;
    cudaGetSymbolAddress((void**)&p_xh, d_xh);
    cudaGetSymbolAddress((void**)&p_h, d_h);
    cudaGetSymbolAddress((void**)&p_x, d_x);
    cudaGetSymbolAddress((void**)&p_g, d_g);
    cudaGetSymbolAddress((void**)&p_xt, d_xt);
    cudaGetSymbolAddress((void**)&p_ef, d_ef);
    cudaGetSymbolAddress((void**)&p_hy, d_hy);
    cudaGetSymbolAddress((void**)&p_bc, d_bc);
    cudaGetSymbolAddress((void**)&p_cb, d_cb);

    // ---- CSR build ----
    zero_counts_kernel<<<(NN + 255) / 256, 256>>>();
    count_kernel<<<(EA + 255) / 256, 256>>>(ei);
    scan3_kernel<<<3, 1024>>>();
    prep_kernel<<<(NN + 255) / 256, 256>>>();
    fill_kernel<<<(EA + 255) / 256, 256>>>(ei);

    // ---- GAT layer 1: h = relu(gat(mol_x)) ----
    run_gemm<false, 1>(mol_x, FIN, FIN, nullptr, 0, W1, 512, p_xh, NN, 512, FIN, nullptr, 0, nullptr);
    build_wv_kernel<<<FIN, 256>>>(W1, as1, ad1);
    attn2_kernel<<<(NN + 3) / 4, 128>>>(mol_x, FIN);
    softmax_kernel<<<(NN + 7) / 8, 256>>>();
    gat_aggregate_kernel<<<NN, 128>>>(p_xh, b1, p_h, 1);

    build_bc_kernel<<<(512 * 256 + 255) / 256, 256>>>(fc1_w, fc2_w, fc1_b, fc2_b);

    // ---- GAT layer 2: x = relu(gat(h)); gate -> d_g ----
    run_gemm<true, 1>(p_h, 256, 256, nullptr, 0, W2, 512, p_xh, NN, 512, 256, nullptr, 0, nullptr);
    build_wv_kernel<<<256, 256>>>(W2, as2, ad2);
    attn2_kernel<<<(NN + 3) / 4, 128>>>(p_h, 256);
    softmax_kernel<<<(NN + 7) / 8, 256>>>();
    gat_aggregate_kernel<<<NN, 128>>>(p_xh, b2, p_x, 1);
    run_gemm<true, 2>(p_x, 256, 256, p_h, 256, p_bc, 256, p_g, NN, 256, 512, p_cb, 0, mol_bias);
    // h is now d_g

    // ---- GAT layer 3: x = gat(h) (no relu); gate -> d_h ----
    run_gemm<true, 1>(p_g, 256, 256, nullptr, 0, W3, 512, p_xh, NN, 512, 256, nullptr, 0, nullptr);
    build_wv_kernel<<<256, 256>>>(W3, as3, ad3);
    attn2_kernel<<<(NN + 3) / 4, 128>>>(p_g, 256);
    softmax_kernel<<<(NN + 7) / 8, 256>>>();
    gat_aggregate_kernel<<<NN, 128>>>(p_xh, b3, p_x, 0);
    run_gemm<true, 2>(p_x, 256, 256, p_g, 256, p_bc, 256, p_h, NN, 256, 512, p_cb, 0, mol_bias);
    // h is now d_h

    // ---- hypergraph branch ----
    run_gemm<true, 1>(p_h, 256, 256, mol_x, FIN, theta1, 128, p_xt, NN, 128, 334, nullptr, 0, nullptr);
    hyper_gather_kernel<true ><<<NN, 64>>>((const __half2*)p_xt, p_ef, nullptr, 0, 0);
    hyper_gather_kernel<false><<<NN, 64>>>((const __half2*)p_ef, p_hy, hb1, 1, 1);
    run_gemm<true, 1>(p_hy, 128, 128, nullptr, 0, theta2, 128, p_xt, NN, 128, 128, nullptr, 0, nullptr);
    hyper_gather_kernel<true ><<<NN, 64>>>((const __half2*)p_xt, p_ef, nullptr, 0, 0);
    hyper_gather_kernel<false><<<NN, 64>>>((const __half2*)p_ef, p_hy, hb2, 1, 1);

    // ---- output: [h | hy] ----
    output_kernel<<<(int)(((size_t)NN * 384 + 255) / 256), 256>>>(p_h, p_hy, (float*)d_out);
}

// round 4
// speedup vs baseline: 3.3679x; 1.0939x over previous
#include <cuda_runtime.h>
#include <cuda_fp16.h>
#include <math.h>
#include <stdint.h>

#define NN 100000
#define EE 3200000
#define EA (EE + NN)
#define FIN 78
#define FG 256
#define FH 128

// ---------------- scratch (device globals; no allocation) ----------------
__device__ __half d_mx16[(size_t)NN * 80];    // padded fp16 mol_x
__device__ __half d_hf[(size_t)NN * 256];     // fp16 copy of current h (gather source)
__device__ __half d_agg[(size_t)NN * 512];    // aggregated features (2 heads)
__device__ float d_h [(size_t)NN * 256];
__device__ float d_x [(size_t)NN * 256];
__device__ float d_g [(size_t)NN * 256];
__device__ __half d_xt[(size_t)NN * 128];
__device__ __half d_ef[(size_t)NN * 128];
__device__ float d_hy[(size_t)NN * 128];
__device__ float d_bc[512 * 256];
__device__ float d_cb[256];
__device__ float d_wv[256 * 4];
__device__ float d_asrc[NN * 2];
__device__ float d_adst[NN * 2];
__device__ float2 d_alpha[EA];
__device__ int csrA_off[NN + 1]; __device__ int csrA_val[EA];
__device__ int csrB_off[NN + 1]; __device__ int csrB_val[EE];
__device__ int csrC_off[NN + 1]; __device__ int csrC_val[EE];
__device__ int cntA[NN], cntB[NN], cntC[NN];
__device__ int curA[NN], curB[NN], curC[NN];
__device__ float d_binv[NN], d_dinv[NN];

// ---------------- CSR construction ----------------
__global__ void zero_counts_kernel() {
    int i = blockIdx.x * blockDim.x + threadIdx.x;
    if (i < NN) { cntA[i] = 0; cntB[i] = 0; cntC[i] = 0; }
}

__global__ void count_kernel(const int* __restrict__ ei) {
    int i = blockIdx.x * blockDim.x + threadIdx.x;
    if (i >= EA) return;
    if (i < EE) {
        int s = ei[i];
        int d = ei[EE + i];
        atomicAdd(&cntA[d], 1);
        atomicAdd(&cntB[d], 1);
        atomicAdd(&cntC[s], 1);
    } else {
        atomicAdd(&cntA[i - EE], 1);
    }
}

__global__ void scan3_kernel() {
    const int* in; int* out;
    if (blockIdx.x == 0)      { in = cntA; out = csrA_off; }
    else if (blockIdx.x == 1) { in = cntB; out = csrB_off; }
    else                      { in = cntC; out = csrC_off; }
    const int n = NN;
    __shared__ int wsum[32];
    __shared__ int carry;
    int tid = threadIdx.x, lane = tid & 31, wid = tid >> 5;
    if (tid == 0) carry = 0;
    __syncthreads();
    for (int base = 0; base < n; base += 1024) {
        int i = base + tid;
        int v = (i < n) ? in[i] : 0;
        int x = v;
        #pragma unroll
        for (int d = 1; d < 32; d <<= 1) {
            int y = __shfl_up_sync(0xFFFFFFFFu, x, d);
            if (lane >= d) x += y;
        }
        if (lane == 31) wsum[wid] = x;
        __syncthreads();
        if (wid == 0) {
            int w = wsum[lane];
            #pragma unroll
            for (int d = 1; d < 32; d <<= 1) {
                int y = __shfl_up_sync(0xFFFFFFFFu, w, d);
                if (lane >= d) w += y;
            }
            wsum[lane] = w;
        }
        __syncthreads();
        int excl = carry + (wid ? wsum[wid - 1] : 0) + x - v;
        if (i < n) out[i] = excl;
        if (i == n - 1) out[n] = excl + v;
        __syncthreads();
        if (tid == 0) carry += wsum[31];
        __syncthreads();
    }
}

__global__ void prep_kernel() {
    int i = blockIdx.x * blockDim.x + threadIdx.x;
    if (i >= NN) return;
    curA[i] = csrA_off[i];
    curB[i] = csrB_off[i];
    curC[i] = csrC_off[i];
    d_binv[i] = cntB[i] > 0 ? 1.0f / (float)cntB[i] : 0.0f;
    d_dinv[i] = cntC[i] > 0 ? 1.0f / (float)cntC[i] : 0.0f;
}

__global__ void fill_kernel(const int* __restrict__ ei) {
    int i = blockIdx.x * blockDim.x + threadIdx.x;
    if (i >= EA) return;
    if (i < EE) {
        int s = ei[i];
        int d = ei[EE + i];
        csrA_val[atomicAdd(&curA[d], 1)] = s;
        csrB_val[atomicAdd(&curB[d], 1)] = s;
        csrC_val[atomicAdd(&curC[s], 1)] = d;
    } else {
        int n = i - EE;
        csrA_val[atomicAdd(&curA[n], 1)] = n;
    }
}

// ---------------- fp16 tensor-core GEMM (m16n8k16, pipelined) ----------------
__device__ __forceinline__ void mma_f16(float* c, const uint32_t* a, uint32_t b0, uint32_t b1) {
    asm volatile(
        "mma.sync.aligned.m16n8k16.row.col.f32.f16.f16.f32 "
        "{%0,%1,%2,%3},{%4,%5,%6,%7},{%8,%9},{%0,%1,%2,%3};"
        : "+f"(c[0]), "+f"(c[1]), "+f"(c[2]), "+f"(c[3])
        : "r"(a[0]), "r"(a[1]), "r"(a[2]), "r"(a[3]), "r"(b0), "r"(b1));
}

#define PA 18                 // pitch in half2 units (16 + 2 pad)
#define TILE_U (128 * PA)     // uint32 per buffer

// ASRC: 0 = fp32 (optional concat A2), 2 = fp16 (dense, no concat)
// EPI:  0 = float out (scale+bias+relu, optional half copy)
//       1 = half out
//       2 = gate blend -> float h_new + half copy
template <int ASRC, int EPI>
__global__ __launch_bounds__(256) void gemm_f16_kernel(
    const void* __restrict__ Ap, int lda, int K1,
    const float* __restrict__ A2, int lda2,
    const float* __restrict__ B1, const float* __restrict__ B2, int ldb,
    int SP, int KV1, int KV2,
    float* __restrict__ C, __half* __restrict__ Chalf,
    int M, int N, int Ktot,
    const float* __restrict__ bias, int relu, float scale,
    const float* __restrict__ molb)
{
    __shared__ uint32_t Asm[2 * TILE_U];
    __shared__ uint32_t Bsm[2 * TILE_U];
    int tid = threadIdx.x;
    int lane = tid & 31, wid = tid >> 5;
    int wm = wid & 3, wn = wid >> 2;
    int row0 = blockIdx.y * 128, col0 = blockIdx.x * 128;
    int g = lane >> 2, tg = lane & 3;

    float acc[2][8][4];
    #pragma unroll
    for (int mi = 0; mi < 2; mi++)
        #pragma unroll
        for (int ni = 0; ni < 8; ni++)
            #pragma unroll
            for (int q = 0; q < 4; q++) acc[mi][ni][q] = 0.0f;

    const float* Af = (const float*)Ap;
    const __half* Ah = (const __half*)Ap;

    float4 raf[4];
    uint2 rah[4];
    float4 rb[4];

    auto loadA = [&](int k0) {
        #pragma unroll
        for (int i = 0; i < 4; i++) {
            int l4 = tid + i * 256;
            int r = l4 >> 3, c4 = (l4 & 7) << 2;
            int grow = row0 + r, gk = k0 + c4;
            if (ASRC == 2) {
                uint2 u = make_uint2(0u, 0u);
                if (grow < M) u = *(const uint2*)(Ah + (size_t)grow * lda + gk);
                rah[i] = u;
            } else {
                float4 v = make_float4(0.f, 0.f, 0.f, 0.f);
                if (grow < M) {
                    if (gk + 3 < K1) {
                        v = *(const float4*)(Af + (size_t)grow * lda + gk);
                    } else {
                        float* pv = &v.x;
                        #pragma unroll
                        for (int j = 0; j < 4; j++) {
                            int kk = gk + j;
                            float x = 0.0f;
                            if (kk < K1) x = Af[(size_t)grow * lda + kk];
                            else if (kk < Ktot) x = A2[(size_t)grow * lda2 + (kk - K1)];
                            pv[j] = x;
                        }
                    }
                }
                raf[i] = v;
            }
        }
    };
    auto storeA = [&](uint32_t* As) {
        #pragma unroll
        for (int i = 0; i < 4; i++) {
            int l4 = tid + i * 256;
            int r = l4 >> 3, c2 = (l4 & 7) << 1;
            if (ASRC == 2) {
                As[r * PA + c2] = rah[i].x;
                As[r * PA + c2 + 1] = rah[i].y;
            } else {
                __half2 h0 = __floats2half2_rn(raf[i].x, raf[i].y);
                __half2 h1 = __floats2half2_rn(raf[i].z, raf[i].w);
                As[r * PA + c2] = *(uint32_t*)&h0;
                As[r * PA + c2 + 1] = *(uint32_t*)&h1;
            }
        }
    };
    auto loadB = [&](int k0) {
        #pragma unroll
        for (int i = 0; i < 4; i++) {
            int l4 = tid + i * 256;
            int k = l4 >> 5, n4 = (l4 & 31) << 2;
            int kk = k0 + k;
            float4 v = make_float4(0.f, 0.f, 0.f, 0.f);
            if (kk < SP) {
                if (kk < KV1) v = *(const float4*)(B1 + (size_t)kk * ldb + col0 + n4);
            } else if (kk < Ktot) {
                int j = kk - SP;
                if (j < KV2) v = *(const float4*)(B2 + (size_t)j * ldb + col0 + n4);
            }
            rb[i] = v;
        }
    };
    auto storeB = [&](uint32_t* Bs) {
        __half* BsH = (__half*)Bs;
        #pragma unroll
        for (int i = 0; i < 4; i++) {
            int l4 = tid + i * 256;
            int k = l4 >> 5, n4 = (l4 & 31) << 2;
            BsH[(n4 + 0) * (2 * PA) + k] = __float2half_rn(rb[i].x);
            BsH[(n4 + 1) * (2 * PA) + k] = __float2half_rn(rb[i].y);
            BsH[(n4 + 2) * (2 * PA) + k] = __float2half_rn(rb[i].z);
            BsH[(n4 + 3) * (2 * PA) + k] = __float2half_rn(rb[i].w);
        }
    };

    int T = (Ktot + 31) >> 5;
    loadA(0); loadB(0);
    storeA(Asm); storeB(Bsm);
    __syncthreads();

    for (int t = 0; t < T; t++) {
        int buf = t & 1;
        bool more = (t + 1 < T);
        if (more) { loadA((t + 1) << 5); loadB((t + 1) << 5); }
        const uint32_t* As = Asm + buf * TILE_U;
        const uint32_t* Bs = Bsm + buf * TILE_U;
        #pragma unroll
        for (int ks = 0; ks < 2; ks++) {
            uint32_t af[2][4];
            #pragma unroll
            for (int mi = 0; mi < 2; mi++) {
                int r = wm * 32 + mi * 16 + g;
                int c = ks * 8 + tg;
                af[mi][0] = As[r * PA + c];
                af[mi][1] = As[(r + 8) * PA + c];
                af[mi][2] = As[r * PA + c + 4];
                af[mi][3] = As[(r + 8) * PA + c + 4];
            }
            #pragma unroll
            for (int ni = 0; ni < 8; ni++) {
                int n = wn * 64 + ni * 8 + g;
                uint32_t b0 = Bs[n * PA + ks * 8 + tg];
                uint32_t b1 = Bs[n * PA + ks * 8 + tg + 4];
                mma_f16(acc[0][ni], af[0], b0, b1);
                mma_f16(acc[1][ni], af[1], b0, b1);
            }
        }
        if (more) {
            storeA(Asm + (buf ^ 1) * TILE_U);
            storeB(Bsm + (buf ^ 1) * TILE_U);
        }
        __syncthreads();
    }

    // epilogue
    #pragma unroll
    for (int mi = 0; mi < 2; mi++) {
        int r0 = row0 + wm * 32 + mi * 16 + g;
        #pragma unroll
        for (int ni = 0; ni < 8; ni++) {
            int c = col0 + wn * 64 + ni * 8 + tg * 2;
            float v0 = acc[mi][ni][0], v1 = acc[mi][ni][1];
            float v2 = acc[mi][ni][2], v3 = acc[mi][ni][3];
            if (EPI == 0) {
                float b0v = bias ? bias[c] : 0.0f;
                float b1v = bias ? bias[c + 1] : 0.0f;
                v0 = v0 * scale + b0v; v1 = v1 * scale + b1v;
                v2 = v2 * scale + b0v; v3 = v3 * scale + b1v;
                if (relu) {
                    v0 = fmaxf(v0, 0.f); v1 = fmaxf(v1, 0.f);
                    v2 = fmaxf(v2, 0.f); v3 = fmaxf(v3, 0.f);
                }
                if (r0 < M) {
                    *(float2*)(C + (size_t)r0 * N + c) = make_float2(v0, v1);
                    if (Chalf) *(__half2*)(Chalf + (size_t)r0 * N + c) = __floats2half2_rn(v0, v1);
                }
                if (r0 + 8 < M) {
                    *(float2*)(C + (size_t)(r0 + 8) * N + c) = make_float2(v2, v3);
                    if (Chalf) *(__half2*)(Chalf + (size_t)(r0 + 8) * N + c) = __floats2half2_rn(v2, v3);
                }
            } else if (EPI == 1) {
                if (r0 < M) *(__half2*)(Chalf + (size_t)r0 * N + c) = __floats2half2_rn(v0, v1);
                if (r0 + 8 < M) *(__half2*)(Chalf + (size_t)(r0 + 8) * N + c) = __floats2half2_rn(v2, v3);
            } else {
                const float* Af2 = (const float*)Ap;
                float cb0 = bias[c] + molb[c];
                float cb1 = bias[c + 1] + molb[c + 1];
                #pragma unroll
                for (int half_ = 0; half_ < 2; half_++) {
                    int r = r0 + half_ * 8;
                    if (r >= M) continue;
                    float va = half_ ? v2 : v0, vb = half_ ? v3 : v1;
                    float z0 = 1.0f / (1.0f + __expf(-(va + cb0)));
                    float z1 = 1.0f / (1.0f + __expf(-(vb + cb1)));
                    float x0 = Af2[(size_t)r * lda + c], x1 = Af2[(size_t)r * lda + c + 1];
                    float h0 = A2[(size_t)r * lda2 + c], h1 = A2[(size_t)r * lda2 + c + 1];
                    float o0 = z0 * x0 + (1.0f - z0) * h0;
                    float o1 = z1 * x1 + (1.0f - z1) * h1;
                    *(float2*)(C + (size_t)r * N + c) = make_float2(o0, o1);
                    *(__half2*)(Chalf + (size_t)r * N + c) = __floats2half2_rn(o0, o1);
                }
            }
        }
    }
}

template <int ASRC, int EPI>
static void run_gemm(const void* A, int lda, int K1, const float* A2, int lda2,
                     const float* B1, const float* B2, int ldb, int SP, int KV1, int KV2,
                     float* C, __half* Chalf, int M, int N, int Ktot,
                     const float* bias, int relu, float scale, const float* molb) {
    dim3 grid(N / 128, (M + 127) / 128);
    gemm_f16_kernel<ASRC, EPI><<<grid, 256>>>(
        A, lda, K1, A2, lda2, B1, B2, ldb, SP, KV1, KV2,
        C, Chalf, M, N, Ktot, bias, relu, scale, molb);
}

// fused gate weight Bc[512][256] = [fc1^T ; fc2^T], combined bias
__global__ void build_bc_kernel(const float* __restrict__ fc1w, const float* __restrict__ fc2w,
                                const float* __restrict__ fc1b, const float* __restrict__ fc2b) {
    int idx = blockIdx.x * blockDim.x + threadIdx.x;
    if (idx >= 512 * 256) return;
    int k = idx >> 8, n = idx & 255;
    d_bc[idx] = (k < 256) ? fc1w[n * 256 + k] : fc2w[n * 256 + (k - 256)];
    if (idx < 256) d_cb[idx] = fc1b[idx] + fc2b[idx];
}

// mol_x -> padded fp16 [N][80]
__global__ void conv_mx_kernel(const float* __restrict__ x) {
    int idx = blockIdx.x * blockDim.x + threadIdx.x;
    if (idx >= NN * 40) return;
    int n = idx / 40, c2 = idx % 40;
    float a = 0.f, b = 0.f;
    int c = c2 * 2;
    if (c < FIN) a = x[(size_t)n * FIN + c];
    if (c + 1 < FIN) b = x[(size_t)n * FIN + c + 1];
    ((__half2*)d_mx16)[idx] = __floats2half2_rn(a, b);
}

// ---------------- exact attention logits ----------------
__global__ void build_wv_kernel(const float* __restrict__ W, const float* __restrict__ as,
                                const float* __restrict__ ad) {
    int k = blockIdx.x, t = threadIdx.x;
    float w0 = W[(size_t)k * 512 + t], w1 = W[(size_t)k * 512 + 256 + t];
    float p0 = w0 * as[t], p1 = w1 * as[256 + t];
    float p2 = w0 * ad[t], p3 = w1 * ad[256 + t];
    __shared__ float red[8][4];
    int lane = t & 31, wid = t >> 5;
    #pragma unroll
    for (int d = 16; d; d >>= 1) {
        p0 += __shfl_down_sync(0xFFFFFFFFu, p0, d);
        p1 += __shfl_down_sync(0xFFFFFFFFu, p1, d);
        p2 += __shfl_down_sync(0xFFFFFFFFu, p2, d);
        p3 += __shfl_down_sync(0xFFFFFFFFu, p3, d);
    }
    if (lane == 0) { red[wid][0] = p0; red[wid][1] = p1; red[wid][2] = p2; red[wid][3] = p3; }
    __syncthreads();
    if (t == 0) {
        float r0 = 0, r1 = 0, r2 = 0, r3 = 0;
        #pragma unroll
        for (int w = 0; w < 8; w++) { r0 += red[w][0]; r1 += red[w][1]; r2 += red[w][2]; r3 += red[w][3]; }
        d_wv[k * 4 + 0] = r0; d_wv[k * 4 + 1] = r1; d_wv[k * 4 + 2] = r2; d_wv[k * 4 + 3] = r3;
    }
}

__global__ void attn2_kernel(const float* __restrict__ x, int K) {
    int warp = threadIdx.x >> 5, lane = threadIdx.x & 31;
    int n = blockIdx.x * 4 + warp;
    if (n >= NN) return;
    const float* xr = x + (size_t)n * K;
    float s0 = 0, s1 = 0, s2 = 0, s3 = 0;
    for (int c = lane; c < K; c += 32) {
        float xv = xr[c];
        float4 wv = ((const float4*)d_wv)[c];
        s0 += xv * wv.x; s1 += xv * wv.y; s2 += xv * wv.z; s3 += xv * wv.w;
    }
    #pragma unroll
    for (int d = 16; d; d >>= 1) {
        s0 += __shfl_down_sync(0xFFFFFFFFu, s0, d);
        s1 += __shfl_down_sync(0xFFFFFFFFu, s1, d);
        s2 += __shfl_down_sync(0xFFFFFFFFu, s2, d);
        s3 += __shfl_down_sync(0xFFFFFFFFu, s3, d);
    }
    if (lane == 0) {
        d_asrc[n * 2] = s0; d_asrc[n * 2 + 1] = s1;
        d_adst[n * 2] = s2; d_adst[n * 2 + 1] = s3;
    }
}

__device__ __forceinline__ float lrelu02(float v) { return v >= 0.0f ? v : 0.2f * v; }

__global__ void softmax_kernel() {
    int n = blockIdx.x * (blockDim.x >> 5) + (threadIdx.x >> 5);
    int lane = threadIdx.x & 31;
    if (n >= NN) return;
    int s0 = csrA_off[n], s1 = csrA_off[n + 1];
    float ad0 = d_adst[n * 2], ad1 = d_adst[n * 2 + 1];
    float m0 = -1e30f, m1 = -1e30f;
    for (int p = s0 + lane; p < s1; p += 32) {
        int src = csrA_val[p];
        float e0 = lrelu02(d_asrc[src * 2] + ad0);
        float e1 = lrelu02(d_asrc[src * 2 + 1] + ad1);
        m0 = fmaxf(m0, e0); m1 = fmaxf(m1, e1);
    }
    #pragma unroll
    for (int d = 16; d; d >>= 1) {
        m0 = fmaxf(m0, __shfl_xor_sync(0xFFFFFFFFu, m0, d));
        m1 = fmaxf(m1, __shfl_xor_sync(0xFFFFFFFFu, m1, d));
    }
    float sum0 = 0.0f, sum1 = 0.0f;
    for (int p = s0 + lane; p < s1; p += 32) {
        int src = csrA_val[p];
        float e0 = lrelu02(d_asrc[src * 2] + ad0);
        float e1 = lrelu02(d_asrc[src * 2 + 1] + ad1);
        float x0 = __expf(e0 - m0), x1 = __expf(e1 - m1);
        d_alpha[p] = make_float2(x0, x1);
        sum0 += x0; sum1 += x1;
    }
    #pragma unroll
    for (int d = 16; d; d >>= 1) {
        sum0 += __shfl_xor_sync(0xFFFFFFFFu, sum0, d);
        sum1 += __shfl_xor_sync(0xFFFFFFFFu, sum1, d);
    }
    float r0 = 1.0f / sum0, r1 = 1.0f / sum1;
    for (int p = s0 + lane; p < s1; p += 32) {
        float2 a = d_alpha[p];
        a.x *= r0; a.y *= r1;
        d_alpha[p] = a;
    }
}

// aggregate raw features once per edge, two head accumulators (256-wide source)
__global__ void gat_agg256_kernel(const __half2* __restrict__ src) {
    int n = blockIdx.x;
    int t = threadIdx.x;  // 128
    int s0 = csrA_off[n], s1 = csrA_off[n + 1];
    float a0x = 0, a0y = 0, a1x = 0, a1y = 0;
    __shared__ int ssrc[128];
    __shared__ float2 salp[128];
    for (int base = s0; base < s1; base += 128) {
        int cnt = min(128, s1 - base);
        __syncthreads();
        if (t < cnt) { ssrc[t] = csrA_val[base + t]; salp[t] = d_alpha[base + t]; }
        __syncthreads();
        #pragma unroll 2
        for (int j = 0; j < cnt; j++) {
            float2 f = __half22float2(src[(size_t)ssrc[j] * 128 + t]);
            float2 a = salp[j];
            a0x += a.x * f.x; a0y += a.x * f.y;
            a1x += a.y * f.x; a1y += a.y * f.y;
        }
    }
    __half2* agg = (__half2*)d_agg;
    agg[(size_t)n * 256 + t] = __floats2half2_rn(a0x, a0y);
    agg[(size_t)n * 256 + 128 + t] = __floats2half2_rn(a1x, a1y);
}

// 78-wide (padded 80) source version, 64 threads, 40 active columns
__global__ void gat_agg78_kernel(const __half2* __restrict__ src) {
    int n = blockIdx.x;
    int t = threadIdx.x;  // 64
    int s0 = csrA_off[n], s1 = csrA_off[n + 1];
    float a0x = 0, a0y = 0, a1x = 0, a1y = 0;
    __shared__ int ssrc[64];
    __shared__ float2 salp[64];
    bool act = t < 40;
    for (int base = s0; base < s1; base += 64) {
        int cnt = min(64, s1 - base);
        __syncthreads();
        if (t < cnt) { ssrc[t] = csrA_val[base + t]; salp[t] = d_alpha[base + t]; }
        __syncthreads();
        if (act) {
            for (int j = 0; j < cnt; j++) {
                float2 f = __half22float2(src[(size_t)ssrc[j] * 40 + t]);
                float2 a = salp[j];
                a0x += a.x * f.x; a0y += a.x * f.y;
                a1x += a.y * f.x; a1y += a.y * f.y;
            }
        }
    }
    if (act) {
        __half2* agg = (__half2*)d_agg;
        agg[(size_t)n * 80 + t] = __floats2half2_rn(a0x, a0y);
        agg[(size_t)n * 80 + 40 + t] = __floats2half2_rn(a1x, a1y);
    }
}

// ---------------- hypergraph ----------------
template <bool OUTH>
__global__ void hyper_gather_kernel(const __half2* __restrict__ in, void* __restrict__ outp,
                                    const float* __restrict__ bias, int which, int relu) {
    const int* off = which ? csrC_off : csrB_off;
    const int* val = which ? csrC_val : csrB_val;
    int n = blockIdx.x;
    int t = threadIdx.x;  // 64
    int s0 = off[n], s1 = off[n + 1];
    float ax = 0, ay = 0;
    __shared__ int sv[64];
    for (int base = s0; base < s1; base += 64) {
        int cnt = min(64, s1 - base);
        __syncthreads();
        if (t < cnt) sv[t] = val[base + t];
        __syncthreads();
        #pragma unroll 4
        for (int j = 0; j < cnt; j++) {
            float2 f = __half22float2(in[(size_t)sv[j] * 64 + t]);
            ax += f.x; ay += f.y;
        }
    }
    float inv = which ? d_dinv[n] : d_binv[n];
    ax *= inv; ay *= inv;
    if (bias) { ax += bias[t * 2]; ay += bias[t * 2 + 1]; }
    if (relu) { ax = fmaxf(ax, 0.f); ay = fmaxf(ay, 0.f); }
    if (OUTH) ((__half2*)outp)[(size_t)n * 64 + t] = __floats2half2_rn(ax, ay);
    else ((float2*)outp)[(size_t)n * 64 + t] = make_float2(ax, ay);
}

__global__ void output_kernel(const float* __restrict__ h, const float* __restrict__ hy,
                              float* __restrict__ out) {
    size_t i = (size_t)blockIdx.x * blockDim.x + threadIdx.x;
    if (i >= (size_t)NN * 384) return;
    int n = (int)(i / 384);
    int c = (int)(i % 384);
    out[i] = (c < 256) ? h[(size_t)n * 256 + c] : hy[(size_t)n * FH + (c - 256)];
}

// ---------------- host side ----------------
extern "C" void kernel_launch(void* const* d_in, const int* in_sizes, int n_in,
                              void* d_out, int out_size) {
    const float* mol_x = (const float*)d_in[0];
    const int*   ei    = (const int*)d_in[1];
    const float* W1 = (const float*)d_in[3];
    const float* as1 = (const float*)d_in[4];
    const float* ad1 = (const float*)d_in[5];
    const float* b1 = (const float*)d_in[6];
    const float* W2 = (const float*)d_in[7];
    const float* as2 = (const float*)d_in[8];
    const float* ad2 = (const float*)d_in[9];
    const float* b2 = (const float*)d_in[10];
    const float* W3 = (const float*)d_in[11];
    const float* as3 = (const float*)d_in[12];
    const float* ad3 = (const float*)d_in[13];
    const float* b3 = (const float*)d_in[14];
    const float* fc1_w = (const float*)d_in[15];
    const float* fc1_b = (const float*)d_in[16];
    const float* fc2_w = (const float*)d_in[17];
    const float* fc2_b = (const float*)d_in[18];
    const float* mol_bias = (const float*)d_in[19];
    const float* theta1 = (const float*)d_in[20];
    const float* hb1 = (const float*)d_in[21];
    const float* theta2 = (const float*)d_in[22];
    const float* hb2 = (const float*)d_in[23];

    __half *p_mx, *p_hf, *p_agg, *p_xt, *p_ef;
    float *p_h, *p_x, *p_g, *p_hy, *p_bc, *p_cb;
    cudaGetSymbolAddress((void**)&p_mx, d_mx16);
    cudaGetSymbolAddress((void**)&p_hf, d_hf);
    cudaGetSymbolAddress((void**)&p_agg, d_agg);
    cudaGetSymbolAddress((void**)&p_h, d_h);
    cudaGetSymbolAddress((void**)&p_x, d_x);
    cudaGetSymbolAddress((void**)&p_g, d_g);
    cudaGetSymbolAddress((void**)&p_xt, d_xt);
    cudaGetSymbolAddress((void**)&p_ef, d_ef);
    cudaGetSymbolAddress((void**)&p_hy, d_hy);
    cudaGetSymbolAddress((void**)&p_bc, d_bc);
    cudaGetSymbolAddress((void**)&p_cb, d_cb);

    // ---- CSR build ----
    zero_counts_kernel<<<(NN + 255) / 256, 256>>>();
    count_kernel<<<(EA + 255) / 256, 256>>>(ei);
    scan3_kernel<<<3, 1024>>>();
    prep_kernel<<<(NN + 255) / 256, 256>>>();
    fill_kernel<<<(EA + 255) / 256, 256>>>(ei);

    conv_mx_kernel<<<(NN * 40 + 255) / 256, 256>>>(mol_x);
    build_bc_kernel<<<(512 * 256 + 255) / 256, 256>>>(fc1_w, fc2_w, fc1_b, fc2_b);

    // ---- GAT layer 1: agg-then-transform; h = relu(...) ----
    build_wv_kernel<<<FIN, 256>>>(W1, as1, ad1);
    attn2_kernel<<<(NN + 3) / 4, 128>>>(mol_x, FIN);
    softmax_kernel<<<(NN + 7) / 8, 256>>>();
    gat_agg78_kernel<<<NN, 64>>>((const __half2*)p_mx);
    run_gemm<2, 0>(p_agg, 160, 160, nullptr, 0, W1, W1 + 256, 512, 80, FIN, FIN,
                   p_h, p_hf, NN, 256, 160, b1, 1, 0.5f, nullptr);

    // ---- GAT layer 2 ----
    build_wv_kernel<<<256, 256>>>(W2, as2, ad2);
    attn2_kernel<<<(NN + 3) / 4, 128>>>(p_h, 256);
    softmax_kernel<<<(NN + 7) / 8, 256>>>();
    gat_agg256_kernel<<<NN, 128>>>((const __half2*)p_hf);
    run_gemm<2, 0>(p_agg, 512, 512, nullptr, 0, W2, W2 + 256, 512, 256, 256, 256,
                   p_x, nullptr, NN, 256, 512, b2, 1, 0.5f, nullptr);
    run_gemm<0, 2>(p_x, 256, 256, p_h, 256, p_bc, nullptr, 256, 512, 512, 0,
                   p_g, p_hf, NN, 256, 512, p_cb, 0, 1.0f, mol_bias);
    // h (fp32) now in d_g; fp16 copy in d_hf

    // ---- GAT layer 3 ----
    build_wv_kernel<<<256, 256>>>(W3, as3, ad3);
    attn2_kernel<<<(NN + 3) / 4, 128>>>(p_g, 256);
    softmax_kernel<<<(NN + 7) / 8, 256>>>();
    gat_agg256_kernel<<<NN, 128>>>((const __half2*)p_hf);
    run_gemm<2, 0>(p_agg, 512, 512, nullptr, 0, W3, W3 + 256, 512, 256, 256, 256,
                   p_x, nullptr, NN, 256, 512, b3, 0, 0.5f, nullptr);
    run_gemm<0, 2>(p_x, 256, 256, p_g, 256, p_bc, nullptr, 256, 512, 512, 0,
                   p_h, p_hf, NN, 256, 512, p_cb, 0, 1.0f, mol_bias);
    // final h (fp32) in d_h

    // ---- hypergraph branch ----
    run_gemm<0, 1>(p_h, 256, 256, mol_x, FIN, theta1, nullptr, 128, 334, 334, 0,
                   nullptr, p_xt, NN, 128, 334, nullptr, 0, 1.0f, nullptr);
    hyper_gather_kernel<true ><<<NN, 64>>>((const __half2*)p_xt, p_ef, nullptr, 0, 0);
    hyper_gather_kernel<false><<<NN, 64>>>((const __half2*)p_ef, p_hy, hb1, 1, 1);
    run_gemm<0, 1>(p_hy, 128, 128, nullptr, 0, theta2, nullptr, 128, 128, 128, 0,
                   nullptr, p_xt, NN, 128, 128, nullptr, 0, 1.0f, nullptr);
    hyper_gather_kernel<true ><<<NN, 64>>>((const __half2*)p_xt, p_ef, nullptr, 0, 0);
    hyper_gather_kernel<false><<<NN, 64>>>((const __half2*)p_ef, p_hy, hb2, 1, 1);

    // ---- output: [h | hy] ----
    output_kernel<<<(int)(((size_t)NN * 384 + 255) / 256), 256>>>(p_h, p_hy, (float*)d_out);
}